// round 10
// baseline (speedup 1.0000x reference)
#include <cuda_runtime.h>
#include <cuda_bf16.h>
#include <math.h>
#include <stdint.h>

// Problem constants
#define Bb     2
#define Ls     4096
#define Dd     1024
#define ORD    2
#define PROJ_N (3*Dd)
#define TAPS   64
#define Mrows  (Bb*Ls)
#define KDIM   1024
#define WROWS  (PROJ_N + 3*Dd)

// ---------------- scratch (device globals) -------------------------------------
__device__ float g_proj[(size_t)Mrows*PROJ_N];
__device__ float g_h[(size_t)TAPS*Dd];
__device__ float g_v[(size_t)Mrows*Dd];
__device__ float g_ux[(size_t)Mrows*Dd];      // u * xc (pre-multiplied)
__device__ __nv_bfloat16 g_w0[(size_t)WROWS*KDIM];
__device__ __nv_bfloat16 g_w1[(size_t)WROWS*KDIM];
__device__ __nv_bfloat16 g_a0[(size_t)Mrows*KDIM];
__device__ __nv_bfloat16 g_a1[(size_t)Mrows*KDIM];
__device__ __nv_bfloat16 g_c0[(size_t)Mrows*KDIM];
__device__ __nv_bfloat16 g_c1[(size_t)Mrows*KDIM];
__device__ __nv_bfloat16 g_v0[(size_t)Mrows*KDIM];
__device__ __nv_bfloat16 g_v1[(size_t)Mrows*KDIM];

// ---------------- helpers -------------------------------------------------------
__device__ __forceinline__ uint32_t smem_u32(const void* p) {
    uint32_t a;
    asm("{ .reg .u64 t; cvta.to.shared.u64 t, %1; cvt.u32.u64 %0, t; }" : "=r"(a) : "l"(p));
    return a;
}
__device__ __forceinline__ void ldsm4(uint32_t* r, uint32_t addr) {
    asm volatile("ldmatrix.sync.aligned.m8n8.x4.shared.b16 {%0,%1,%2,%3}, [%4];"
                 : "=r"(r[0]), "=r"(r[1]), "=r"(r[2]), "=r"(r[3]) : "r"(addr));
}
__device__ __forceinline__ void mma16816(float* c, const uint32_t* a, const uint32_t* b) {
    asm volatile(
        "mma.sync.aligned.m16n8k16.row.col.f32.bf16.bf16.f32 "
        "{%0,%1,%2,%3}, {%4,%5,%6,%7}, {%8,%9}, {%0,%1,%2,%3};"
        : "+f"(c[0]), "+f"(c[1]), "+f"(c[2]), "+f"(c[3])
        : "r"(a[0]), "r"(a[1]), "r"(a[2]), "r"(a[3]), "r"(b[0]), "r"(b[1]));
}

// ================== bf16x3 HMMA GEMM, 2 CTAs/SM ==================================
// C[M,N] = A[M,K] @ Bt[N,K]^T (+bias).  A,B as 2 bf16 components each.
// CTA 128x128, K chunk 32 (64B rows), 3-stage cp.async, 96KB smem -> 2 CTA/SM.
// epi: 0 = C=acc+bias (fp32)
//      1 = val = ux * sigmoid(acc+bias); write fp32 C only   (gate iter 0)
//      2 = val = ux * sigmoid(acc+bias); write bf16 splits v0/v1 only (gate iter 1)
#define STAGES      3
#define CHUNK_K     32
#define SUB_BYTES   8192
#define STAGE_BYTES (4*SUB_BYTES)
#define GEMM_SMEM   (STAGES*STAGE_BYTES)

__global__ void __launch_bounds__(256, 2) gemm_bf16x3_k(
    const __nv_bfloat16* __restrict__ A0, const __nv_bfloat16* __restrict__ A1,
    const __nv_bfloat16* __restrict__ B0, const __nv_bfloat16* __restrict__ B1,
    const float* __restrict__ bias, float* __restrict__ C, int ldc, int Kdim, int epi,
    const float* __restrict__ ux,
    __nv_bfloat16* __restrict__ v0, __nv_bfloat16* __restrict__ v1)
{
    extern __shared__ char smem[];
    const uint32_t stg = smem_u32(smem);
    const int tid = threadIdx.x, wid = tid >> 5, lane = tid & 31;
    const int bm = blockIdx.y * 128, bn = blockIdx.x * 128;
    const int wm = (wid & 3) * 32, wn = (wid >> 2) * 64;
    const int nchunk = Kdim / CHUNK_K;

    const __nv_bfloat16* sA0 = A0 + (size_t)bm * Kdim;
    const __nv_bfloat16* sA1 = A1 + (size_t)bm * Kdim;
    const __nv_bfloat16* sB0 = B0 + (size_t)bn * Kdim;
    const __nv_bfloat16* sB1 = B1 + (size_t)bn * Kdim;

    auto fill = [&](int chunk, int stage) {
        const uint32_t st = stg + stage * STAGE_BYTES;
        const int k0 = chunk * CHUNK_K;
        const __nv_bfloat16* gs[4] = { sA0, sA1, sB0, sB1 };
        #pragma unroll
        for (int sub = 0; sub < 4; sub++) {
            const __nv_bfloat16* g = gs[sub] + k0;
            const uint32_t db = st + sub * SUB_BYTES;
            #pragma unroll
            for (int i = 0; i < 2; i++) {
                int idx = tid + i * 256;
                int row = idx >> 2, cs = idx & 3;
                const void* gp = g + (size_t)row * Kdim + cs * 8;
                uint32_t dp = db + row * 64 + ((cs ^ ((row >> 1) & 3)) << 4);
                asm volatile("cp.async.cg.shared.global [%0], [%1], 16;"
                             :: "r"(dp), "l"(gp) : "memory");
            }
        }
        asm volatile("cp.async.commit_group;" ::: "memory");
    };

    fill(0, 0);
    fill(1, 1);

    float acc[2][8][4];
    #pragma unroll
    for (int i = 0; i < 2; i++)
        #pragma unroll
        for (int j = 0; j < 8; j++)
            #pragma unroll
            for (int p = 0; p < 4; p++) acc[i][j][p] = 0.f;

    uint32_t offA[2][2], offB[4][2];
    #pragma unroll
    for (int mt = 0; mt < 2; mt++) {
        int row = wm + mt * 16 + (lane & 15);
        #pragma unroll
        for (int kk = 0; kk < 2; kk++) {
            int cs = kk * 2 + (lane >> 4);
            offA[mt][kk] = row * 64 + ((cs ^ ((row >> 1) & 3)) << 4);
        }
    }
    #pragma unroll
    for (int jb = 0; jb < 4; jb++) {
        int n = wn + jb * 16 + ((lane >> 4) << 3) + (lane & 7);
        #pragma unroll
        for (int kk = 0; kk < 2; kk++) {
            int cs = kk * 2 + ((lane >> 3) & 1);
            offB[jb][kk] = n * 64 + ((cs ^ ((n >> 1) & 3)) << 4);
        }
    }

    for (int c = 0; c < nchunk; c++) {
        const int s = c % STAGES;
        asm volatile("cp.async.wait_group 1;" ::: "memory");
        __syncthreads();

        const int nc = c + STAGES - 1;
        if (nc < nchunk) fill(nc, nc % STAGES);

        const uint32_t st = stg + s * STAGE_BYTES;
        #pragma unroll
        for (int kk = 0; kk < 2; kk++) {
            uint32_t ah[2][4], al[2][4];
            #pragma unroll
            for (int mt = 0; mt < 2; mt++) {
                ldsm4(ah[mt], st + offA[mt][kk]);
                ldsm4(al[mt], st + SUB_BYTES + offA[mt][kk]);
            }
            #pragma unroll
            for (int jb = 0; jb < 4; jb++) {
                uint32_t bh[4], bl[4];
                ldsm4(bh, st + 2 * SUB_BYTES + offB[jb][kk]);
                ldsm4(bl, st + 3 * SUB_BYTES + offB[jb][kk]);
                #pragma unroll
                for (int half = 0; half < 2; half++) {
                    const int nt = 2 * jb + half;
                    #pragma unroll
                    for (int mt = 0; mt < 2; mt++) {
                        mma16816(acc[mt][nt], ah[mt], bh + 2 * half);  // h*h
                        mma16816(acc[mt][nt], ah[mt], bl + 2 * half);  // h*l
                        mma16816(acc[mt][nt], al[mt], bh + 2 * half);  // l*h
                    }
                }
            }
        }
    }

    // ---------------- epilogue --------------------------------------------------
    const int r0 = bm + wm + (lane >> 2);
    const int cb0 = bn + wn + (lane & 3) * 2;
    #pragma unroll
    for (int mt = 0; mt < 2; mt++) {
        #pragma unroll
        for (int nt = 0; nt < 8; nt++) {
            const int col = cb0 + nt * 8;
            const float bx = bias[col], by = bias[col + 1];
            #pragma unroll
            for (int half = 0; half < 2; half++) {
                const int row = r0 + mt * 16 + half * 8;
                float vx = acc[mt][nt][half * 2 + 0] + bx;
                float vy = acc[mt][nt][half * 2 + 1] + by;
                if (epi == 0) {
                    float2 o; o.x = vx; o.y = vy;
                    *(float2*)(C + (size_t)row * ldc + col) = o;
                } else {
                    const size_t idx = (size_t)row * Dd + col;
                    float2 pp = *(const float2*)(ux + idx);
                    vx = pp.x * (1.0f / (1.0f + __expf(-vx)));
                    vy = pp.y * (1.0f / (1.0f + __expf(-vy)));
                    if (epi == 1) {
                        float2 o; o.x = vx; o.y = vy;
                        *(float2*)(C + (size_t)row * ldc + col) = o;
                    } else {
                        __nv_bfloat16 h0 = __float2bfloat16_rn(vx);
                        __nv_bfloat16 h1 = __float2bfloat16_rn(vy);
                        __nv_bfloat162 hh2; hh2.x = h0; hh2.y = h1;
                        *(__nv_bfloat162*)(v0 + idx) = hh2;
                        __nv_bfloat162 ll;
                        ll.x = __float2bfloat16_rn(vx - __bfloat162float(h0));
                        ll.y = __float2bfloat16_rn(vy - __bfloat162float(h1));
                        *(__nv_bfloat162*)(v1 + idx) = ll;
                    }
                }
            }
        }
    }
}

// ================== split / merged transpose-split ================================
__global__ void split4_k(const float* __restrict__ s,
                         __nv_bfloat16* __restrict__ b0, __nv_bfloat16* __restrict__ b1, int n4)
{
    int i = blockIdx.x * blockDim.x + threadIdx.x;
    if (i >= n4) return;
    float4 v = ((const float4*)s)[i];
    const float* vv = (const float*)&v;
    #pragma unroll
    for (int p = 0; p < 4; p += 2) {
        __nv_bfloat16 h0 = __float2bfloat16_rn(vv[p]);
        __nv_bfloat16 h1 = __float2bfloat16_rn(vv[p + 1]);
        __nv_bfloat162 hh; hh.x = h0; hh.y = h1;
        *(__nv_bfloat162*)(b0 + (size_t)i * 4 + p) = hh;
        __nv_bfloat162 ll;
        ll.x = __float2bfloat16_rn(vv[p]     - __bfloat162float(h0));
        ll.y = __float2bfloat16_rn(vv[p + 1] - __bfloat162float(h1));
        *(__nv_bfloat162*)(b1 + (size_t)i * 4 + p) = ll;
    }
}

__global__ void tsplit_all_k(const float* __restrict__ ipw, const float* __restrict__ gw,
                             const float* __restrict__ opw,
                             __nv_bfloat16* __restrict__ T0, __nv_bfloat16* __restrict__ T1)
{
    __shared__ float tile[32][33];
    int gn0 = blockIdx.x * 32;
    int k0  = blockIdx.y * 32;
    int tx = threadIdx.x, ty = threadIdx.y;

    const float* W; int N; int nbase;
    if (gn0 < PROJ_N)            { W = ipw;                  N = PROJ_N; nbase = gn0; }
    else if (gn0 < PROJ_N + Dd)  { W = gw;                   N = Dd;     nbase = gn0 - PROJ_N; }
    else if (gn0 < PROJ_N + 2*Dd){ W = gw + (size_t)Dd * Dd; N = Dd;     nbase = gn0 - PROJ_N - Dd; }
    else                         { W = opw;                  N = Dd;     nbase = gn0 - PROJ_N - 2*Dd; }

    #pragma unroll
    for (int j = 0; j < 32; j += 8)
        tile[ty + j][tx] = W[(size_t)(k0 + ty + j) * N + nbase + tx];
    __syncthreads();
    #pragma unroll
    for (int j = 0; j < 32; j += 8) {
        int n = gn0 + ty + j, k = k0 + tx;
        float v = tile[tx][ty + j];
        __nv_bfloat16 h = __float2bfloat16_rn(v);
        size_t o = (size_t)n * KDIM + k;
        T0[o] = h;
        T1[o] = __float2bfloat16_rn(v - __bfloat162float(h));
    }
}

// ================== filter ========================================================
__device__ __forceinline__ float gelu_exact(float x) {
    return 0.5f * x * (1.0f + erff(x * 0.70710678118654752f));
}

__global__ void filter_k(const float* __restrict__ freqs,
                         const float* __restrict__ w1, const float* __restrict__ b1,
                         const float* __restrict__ w2, const float* __restrict__ b2,
                         const float* __restrict__ w3, const float* __restrict__ b3,
                         const float* __restrict__ decay, int ord,
                         float* __restrict__ h)
{
    const int n   = blockIdx.x;
    const int tid = threadIdx.x;
    const float t = (float)n / (float)(Ls - 1);
    __shared__ float h1s[64];
    __shared__ float h2s[64];
    float enc[7];
    const float* f = freqs + ord * 3;
    #pragma unroll
    for (int j = 0; j < 3; j++) {
        float ang = 6.283185307179586f * f[j] * t;
        enc[j] = sinf(ang); enc[3 + j] = cosf(ang);
    }
    enc[6] = t;
    if (tid < 64) {
        float s = b1[ord * 64 + tid];
        #pragma unroll
        for (int k = 0; k < 7; k++) s += enc[k] * w1[(ord * 7 + k) * 64 + tid];
        h1s[tid] = gelu_exact(s);
    }
    __syncthreads();
    if (tid < 64) {
        float s = b2[ord * 64 + tid];
        for (int k = 0; k < 64; k++) s += h1s[k] * w2[(ord * 64 + k) * 64 + tid];
        h2s[tid] = gelu_exact(s);
    }
    __syncthreads();
    for (int d = tid; d < Dd; d += blockDim.x) {
        float s = b3[(size_t)ord * Dd + d];
        for (int k = 0; k < 64; k++) s += h2s[k] * w3[((size_t)ord * 64 + k) * Dd + d];
        float wind = expf(-fabsf(decay[(size_t)ord * Dd + d]) * t * (float)Ls);
        h[(size_t)n * Dd + d] = s * wind;
    }
}

// ================== merged convlong + conv3, fused ux = u*xc ======================
#define CT 32
__global__ void __launch_bounds__(128) convs_k(
    const float* __restrict__ vin, int vstride,
    const float* __restrict__ hflt,
    float* __restrict__ ux,
    const float* __restrict__ proj, int off,
    const float* __restrict__ w, const float* __restrict__ cb,
    __nv_bfloat16* __restrict__ o0, __nv_bfloat16* __restrict__ o1)
{
    __shared__ float vs[CT + TAPS - 1][128];
    const int tx = threadIdx.x;
    const int d  = blockIdx.x * 128 + tx;
    const int t0 = blockIdx.y * CT;
    const int b  = blockIdx.z;

    #pragma unroll 5
    for (int r = 0; r < CT + TAPS - 1; r++) {
        int t = t0 - (TAPS - 1) + r;
        vs[r][tx] = (t >= 0) ? vin[((size_t)b * Ls + t) * vstride + d] : 0.f;
    }
    __syncthreads();

    float acc[CT];
    #pragma unroll
    for (int j = 0; j < CT; j++) acc[j] = 0.f;
    #pragma unroll
    for (int l0 = 0; l0 < TAPS; l0 += 16) {
        float hr[16];
        #pragma unroll
        for (int l = 0; l < 16; l++) hr[l] = hflt[(size_t)(l0 + l) * Dd + d];
        float vv[CT + 15];
        #pragma unroll
        for (int p = 0; p < CT + 15; p++) vv[p] = vs[(TAPS - 1 - 15) - l0 + p][tx];
        #pragma unroll
        for (int l = 0; l < 16; l++)
            #pragma unroll
            for (int j = 0; j < CT; j++)
                acc[j] = fmaf(vv[15 + j - l], hr[l], acc[j]);
    }

    const float wl = w[d], wc = w[Dd + d], wr = w[2 * Dd + d], cbv = cb[d];
    const float* pbase = proj + ((size_t)b * Ls + t0) * PROJ_N + off + d;
    #pragma unroll 4
    for (int j = 0; j < CT; j++) {
        int t = t0 + j;
        const float* p = pbase + (size_t)j * PROJ_N;
        float s = cbv + p[0] * wc;
        if (t > 0)      s += p[-PROJ_N] * wl;
        if (t < Ls - 1) s += p[PROJ_N]  * wr;
        size_t idx = ((size_t)b * Ls + t) * Dd + d;
        ux[idx] = acc[j] * s;                       // pre-multiplied u * xc
        __nv_bfloat16 hh = __float2bfloat16_rn(s);
        o0[idx] = hh;
        o1[idx] = __float2bfloat16_rn(s - __bfloat162float(hh));
    }
}

// =================================================================================
extern "C" void kernel_launch(void* const* d_in, const int* in_sizes, int n_in,
                              void* d_out, int out_size)
{
    const float* x    = (const float*)d_in[0];
    const float* ipw  = (const float*)d_in[1];
    const float* ipb  = (const float*)d_in[2];
    const float* opw  = (const float*)d_in[3];
    const float* opb  = (const float*)d_in[4];
    const float* fre  = (const float*)d_in[5];
    const float* w1   = (const float*)d_in[6];
    const float* b1   = (const float*)d_in[7];
    const float* w2   = (const float*)d_in[8];
    const float* b2   = (const float*)d_in[9];
    const float* w3   = (const float*)d_in[10];
    const float* b3   = (const float*)d_in[11];
    const float* dec  = (const float*)d_in[12];
    const float* cw   = (const float*)d_in[13];
    const float* cb   = (const float*)d_in[14];
    const float* gw   = (const float*)d_in[15];
    const float* gb   = (const float*)d_in[16];
    float* out = (float*)d_out;

    float *p_proj, *p_h, *p_v, *p_ux;
    __nv_bfloat16 *p_w0, *p_w1, *p_a0, *p_a1, *p_c0, *p_c1, *p_v0, *p_v1;
    cudaGetSymbolAddress((void**)&p_proj, g_proj);
    cudaGetSymbolAddress((void**)&p_h,    g_h);
    cudaGetSymbolAddress((void**)&p_v,    g_v);
    cudaGetSymbolAddress((void**)&p_ux,   g_ux);
    cudaGetSymbolAddress((void**)&p_w0,   g_w0);
    cudaGetSymbolAddress((void**)&p_w1,   g_w1);
    cudaGetSymbolAddress((void**)&p_a0,   g_a0);
    cudaGetSymbolAddress((void**)&p_a1,   g_a1);
    cudaGetSymbolAddress((void**)&p_c0,   g_c0);
    cudaGetSymbolAddress((void**)&p_c1,   g_c1);
    cudaGetSymbolAddress((void**)&p_v0,   g_v0);
    cudaGetSymbolAddress((void**)&p_v1,   g_v1);

    cudaFuncSetAttribute(gemm_bf16x3_k, cudaFuncAttributeMaxDynamicSharedMemorySize, GEMM_SMEM);

    // split x into bf16 comps
    {
        int n4 = Mrows * KDIM / 4;
        split4_k<<<(n4 + 255) / 256, 256>>>(x, p_a0, p_a1, n4);
    }
    // transpose-split ALL weights in one launch
    {
        dim3 b(32, 8);
        tsplit_all_k<<<dim3(WROWS / 32, KDIM / 32), b>>>(ipw, gw, opw, p_w0, p_w1);
    }

    // 1) proj = x @ in_proj_w + b
    gemm_bf16x3_k<<<dim3(PROJ_N / 128, Mrows / 128), 256, GEMM_SMEM>>>(
        p_a0, p_a1, p_w0, p_w1, ipb, p_proj, PROJ_N, KDIM, 0,
        nullptr, nullptr, nullptr);

    for (int i = 0; i < ORD; i++) {
        filter_k<<<TAPS, 256>>>(fre, w1, b1, w2, b2, w3, b3, dec, i, p_h);

        const float* vin = (i == 0) ? p_proj : p_v;
        int vstride      = (i == 0) ? PROJ_N : Dd;
        dim3 gc(Dd / 128, Ls / CT, Bb);
        convs_k<<<gc, 128>>>(vin, vstride, p_h, p_ux,
                             p_proj, (i + 1) * Dd,
                             cw + (size_t)i * 3 * Dd, cb + (size_t)i * Dd,
                             p_c0, p_c1);

        // gate GEMM: v = ux * sigmoid(xc@gw + gb)
        //   iter 0 -> epi 1 (write fp32 v for next convs)
        //   iter 1 -> epi 2 (write bf16 splits v0/v1 for out GEMM)
        gemm_bf16x3_k<<<dim3(Dd / 128, Mrows / 128), 256, GEMM_SMEM>>>(
            p_c0, p_c1,
            p_w0 + (size_t)(PROJ_N + i * Dd) * KDIM,
            p_w1 + (size_t)(PROJ_N + i * Dd) * KDIM,
            gb + (size_t)i * Dd, p_v, Dd, KDIM, (i == 0) ? 1 : 2,
            p_ux, p_v0, p_v1);
    }

    // 3) out = v @ out_proj_w + b
    gemm_bf16x3_k<<<dim3(Dd / 128, Mrows / 128), 256, GEMM_SMEM>>>(
        p_v0, p_v1,
        p_w0 + (size_t)(PROJ_N + 2 * Dd) * KDIM,
        p_w1 + (size_t)(PROJ_N + 2 * Dd) * KDIM,
        opb, out, Dd, KDIM, 0,
        nullptr, nullptr, nullptr);
}

// round 11
// speedup vs baseline: 1.1814x; 1.1814x over previous
#include <cuda_runtime.h>
#include <cuda_bf16.h>
#include <cuda_fp16.h>
#include <math.h>
#include <stdint.h>

// Problem constants
#define Bb     2
#define Ls     4096
#define Dd     1024
#define ORD    2
#define PROJ_N (3*Dd)
#define TAPS   64
#define Mrows  (Bb*Ls)
#define KDIM   1024
#define WROWS  (PROJ_N + 3*Dd)

// ---------------- scratch (device globals) -------------------------------------
__device__ float g_proj[(size_t)Mrows*PROJ_N];
__device__ float g_h[(size_t)TAPS*Dd];
__device__ float g_v[(size_t)Mrows*Dd];
__device__ float g_ux[(size_t)Mrows*Dd];            // u * xc (pre-multiplied)
__device__ __nv_bfloat16 g_w0[(size_t)WROWS*KDIM];  // bf16 hi comps (all weights)
__device__ __nv_bfloat16 g_w1[(size_t)WROWS*KDIM];  // bf16 lo comps
__device__ __half        g_wh[(size_t)2*Dd*KDIM];   // fp16 gate weights (transposed)
__device__ __nv_bfloat16 g_a0[(size_t)Mrows*KDIM];
__device__ __nv_bfloat16 g_a1[(size_t)Mrows*KDIM];
__device__ __half        g_ch[(size_t)Mrows*KDIM];  // fp16 xc
__device__ __nv_bfloat16 g_v0[(size_t)Mrows*KDIM];
__device__ __nv_bfloat16 g_v1[(size_t)Mrows*KDIM];

// ---------------- helpers -------------------------------------------------------
__device__ __forceinline__ uint32_t smem_u32(const void* p) {
    uint32_t a;
    asm("{ .reg .u64 t; cvta.to.shared.u64 t, %1; cvt.u32.u64 %0, t; }" : "=r"(a) : "l"(p));
    return a;
}
__device__ __forceinline__ void ldsm4(uint32_t* r, uint32_t addr) {
    asm volatile("ldmatrix.sync.aligned.m8n8.x4.shared.b16 {%0,%1,%2,%3}, [%4];"
                 : "=r"(r[0]), "=r"(r[1]), "=r"(r[2]), "=r"(r[3]) : "r"(addr));
}
__device__ __forceinline__ void mma16816(float* c, const uint32_t* a, const uint32_t* b) {
    asm volatile(
        "mma.sync.aligned.m16n8k16.row.col.f32.bf16.bf16.f32 "
        "{%0,%1,%2,%3}, {%4,%5,%6,%7}, {%8,%9}, {%0,%1,%2,%3};"
        : "+f"(c[0]), "+f"(c[1]), "+f"(c[2]), "+f"(c[3])
        : "r"(a[0]), "r"(a[1]), "r"(a[2]), "r"(a[3]), "r"(b[0]), "r"(b[1]));
}
__device__ __forceinline__ void mma16816h(float* c, const uint32_t* a, const uint32_t* b) {
    asm volatile(
        "mma.sync.aligned.m16n8k16.row.col.f32.f16.f16.f32 "
        "{%0,%1,%2,%3}, {%4,%5,%6,%7}, {%8,%9}, {%0,%1,%2,%3};"
        : "+f"(c[0]), "+f"(c[1]), "+f"(c[2]), "+f"(c[3])
        : "r"(a[0]), "r"(a[1]), "r"(a[2]), "r"(a[3]), "r"(b[0]), "r"(b[1]));
}

// ================== bf16x3 HMMA GEMM, 2 CTAs/SM (in_proj / out_proj) =============
#define STAGES      3
#define CHUNK_K     32
#define SUB_BYTES   8192
#define STAGE_BYTES (4*SUB_BYTES)
#define GEMM_SMEM   (STAGES*STAGE_BYTES)

__global__ void __launch_bounds__(256, 2) gemm_bf16x3_k(
    const __nv_bfloat16* __restrict__ A0, const __nv_bfloat16* __restrict__ A1,
    const __nv_bfloat16* __restrict__ B0, const __nv_bfloat16* __restrict__ B1,
    const float* __restrict__ bias, float* __restrict__ C, int ldc, int Kdim)
{
    extern __shared__ char smem[];
    const uint32_t stg = smem_u32(smem);
    const int tid = threadIdx.x, wid = tid >> 5, lane = tid & 31;
    const int bm = blockIdx.y * 128, bn = blockIdx.x * 128;
    const int wm = (wid & 3) * 32, wn = (wid >> 2) * 64;
    const int nchunk = Kdim / CHUNK_K;

    const __nv_bfloat16* sA0 = A0 + (size_t)bm * Kdim;
    const __nv_bfloat16* sA1 = A1 + (size_t)bm * Kdim;
    const __nv_bfloat16* sB0 = B0 + (size_t)bn * Kdim;
    const __nv_bfloat16* sB1 = B1 + (size_t)bn * Kdim;

    auto fill = [&](int chunk, int stage) {
        const uint32_t st = stg + stage * STAGE_BYTES;
        const int k0 = chunk * CHUNK_K;
        const __nv_bfloat16* gs[4] = { sA0, sA1, sB0, sB1 };
        #pragma unroll
        for (int sub = 0; sub < 4; sub++) {
            const __nv_bfloat16* g = gs[sub] + k0;
            const uint32_t db = st + sub * SUB_BYTES;
            #pragma unroll
            for (int i = 0; i < 2; i++) {
                int idx = tid + i * 256;
                int row = idx >> 2, cs = idx & 3;
                const void* gp = g + (size_t)row * Kdim + cs * 8;
                uint32_t dp = db + row * 64 + ((cs ^ ((row >> 1) & 3)) << 4);
                asm volatile("cp.async.cg.shared.global [%0], [%1], 16;"
                             :: "r"(dp), "l"(gp) : "memory");
            }
        }
        asm volatile("cp.async.commit_group;" ::: "memory");
    };

    fill(0, 0);
    fill(1, 1);

    float acc[2][8][4];
    #pragma unroll
    for (int i = 0; i < 2; i++)
        #pragma unroll
        for (int j = 0; j < 8; j++)
            #pragma unroll
            for (int p = 0; p < 4; p++) acc[i][j][p] = 0.f;

    uint32_t offA[2][2], offB[4][2];
    #pragma unroll
    for (int mt = 0; mt < 2; mt++) {
        int row = wm + mt * 16 + (lane & 15);
        #pragma unroll
        for (int kk = 0; kk < 2; kk++) {
            int cs = kk * 2 + (lane >> 4);
            offA[mt][kk] = row * 64 + ((cs ^ ((row >> 1) & 3)) << 4);
        }
    }
    #pragma unroll
    for (int jb = 0; jb < 4; jb++) {
        int n = wn + jb * 16 + ((lane >> 4) << 3) + (lane & 7);
        #pragma unroll
        for (int kk = 0; kk < 2; kk++) {
            int cs = kk * 2 + ((lane >> 3) & 1);
            offB[jb][kk] = n * 64 + ((cs ^ ((n >> 1) & 3)) << 4);
        }
    }

    for (int c = 0; c < nchunk; c++) {
        const int s = c % STAGES;
        asm volatile("cp.async.wait_group 1;" ::: "memory");
        __syncthreads();

        const int nc = c + STAGES - 1;
        if (nc < nchunk) fill(nc, nc % STAGES);

        const uint32_t st = stg + s * STAGE_BYTES;
        #pragma unroll
        for (int kk = 0; kk < 2; kk++) {
            uint32_t ah[2][4], al[2][4];
            #pragma unroll
            for (int mt = 0; mt < 2; mt++) {
                ldsm4(ah[mt], st + offA[mt][kk]);
                ldsm4(al[mt], st + SUB_BYTES + offA[mt][kk]);
            }
            #pragma unroll
            for (int jb = 0; jb < 4; jb++) {
                uint32_t bh[4], bl[4];
                ldsm4(bh, st + 2 * SUB_BYTES + offB[jb][kk]);
                ldsm4(bl, st + 3 * SUB_BYTES + offB[jb][kk]);
                #pragma unroll
                for (int half = 0; half < 2; half++) {
                    const int nt = 2 * jb + half;
                    #pragma unroll
                    for (int mt = 0; mt < 2; mt++) {
                        mma16816(acc[mt][nt], ah[mt], bh + 2 * half);
                        mma16816(acc[mt][nt], ah[mt], bl + 2 * half);
                        mma16816(acc[mt][nt], al[mt], bh + 2 * half);
                    }
                }
            }
        }
    }

    const int r0 = bm + wm + (lane >> 2);
    const int cb0 = bn + wn + (lane & 3) * 2;
    #pragma unroll
    for (int mt = 0; mt < 2; mt++)
        #pragma unroll
        for (int nt = 0; nt < 8; nt++) {
            const int col = cb0 + nt * 8;
            const float bx = bias[col], by = bias[col + 1];
            #pragma unroll
            for (int half = 0; half < 2; half++) {
                const int row = r0 + mt * 16 + half * 8;
                float2 o;
                o.x = acc[mt][nt][half * 2 + 0] + bx;
                o.y = acc[mt][nt][half * 2 + 1] + by;
                *(float2*)(C + (size_t)row * ldc + col) = o;
            }
        }
}

// ================== fp16 single-pass GEMM (gate GEMMs) ===========================
// y = A@B^T + bias; epi 1: C = ux*sigmoid(y) fp32; epi 2: bf16 splits v0/v1 only.
#define HSUB_BYTES   8192
#define HSTAGE_BYTES (2*HSUB_BYTES)
#define HGEMM_SMEM   (STAGES*HSTAGE_BYTES)

__global__ void __launch_bounds__(256, 2) gemm_f16_k(
    const __half* __restrict__ A, const __half* __restrict__ B,
    const float* __restrict__ bias, float* __restrict__ C, int epi,
    const float* __restrict__ ux,
    __nv_bfloat16* __restrict__ v0, __nv_bfloat16* __restrict__ v1)
{
    extern __shared__ char smem[];
    const uint32_t stg = smem_u32(smem);
    const int tid = threadIdx.x, wid = tid >> 5, lane = tid & 31;
    const int bm = blockIdx.y * 128, bn = blockIdx.x * 128;
    const int wm = (wid & 3) * 32, wn = (wid >> 2) * 64;
    const int nchunk = KDIM / CHUNK_K;

    const __half* sA = A + (size_t)bm * KDIM;
    const __half* sB = B + (size_t)bn * KDIM;

    auto fill = [&](int chunk, int stage) {
        const uint32_t st = stg + stage * HSTAGE_BYTES;
        const int k0 = chunk * CHUNK_K;
        const __half* gs[2] = { sA, sB };
        #pragma unroll
        for (int sub = 0; sub < 2; sub++) {
            const __half* g = gs[sub] + k0;
            const uint32_t db = st + sub * HSUB_BYTES;
            #pragma unroll
            for (int i = 0; i < 2; i++) {
                int idx = tid + i * 256;
                int row = idx >> 2, cs = idx & 3;
                const void* gp = g + (size_t)row * KDIM + cs * 8;
                uint32_t dp = db + row * 64 + ((cs ^ ((row >> 1) & 3)) << 4);
                asm volatile("cp.async.cg.shared.global [%0], [%1], 16;"
                             :: "r"(dp), "l"(gp) : "memory");
            }
        }
        asm volatile("cp.async.commit_group;" ::: "memory");
    };

    fill(0, 0);
    fill(1, 1);

    float acc[2][8][4];
    #pragma unroll
    for (int i = 0; i < 2; i++)
        #pragma unroll
        for (int j = 0; j < 8; j++)
            #pragma unroll
            for (int p = 0; p < 4; p++) acc[i][j][p] = 0.f;

    uint32_t offA[2][2], offB[4][2];
    #pragma unroll
    for (int mt = 0; mt < 2; mt++) {
        int row = wm + mt * 16 + (lane & 15);
        #pragma unroll
        for (int kk = 0; kk < 2; kk++) {
            int cs = kk * 2 + (lane >> 4);
            offA[mt][kk] = row * 64 + ((cs ^ ((row >> 1) & 3)) << 4);
        }
    }
    #pragma unroll
    for (int jb = 0; jb < 4; jb++) {
        int n = wn + jb * 16 + ((lane >> 4) << 3) + (lane & 7);
        #pragma unroll
        for (int kk = 0; kk < 2; kk++) {
            int cs = kk * 2 + ((lane >> 3) & 1);
            offB[jb][kk] = n * 64 + ((cs ^ ((n >> 1) & 3)) << 4);
        }
    }

    for (int c = 0; c < nchunk; c++) {
        const int s = c % STAGES;
        asm volatile("cp.async.wait_group 1;" ::: "memory");
        __syncthreads();

        const int nc = c + STAGES - 1;
        if (nc < nchunk) fill(nc, nc % STAGES);

        const uint32_t st = stg + s * HSTAGE_BYTES;
        #pragma unroll
        for (int kk = 0; kk < 2; kk++) {
            uint32_t a[2][4];
            ldsm4(a[0], st + offA[0][kk]);
            ldsm4(a[1], st + offA[1][kk]);
            #pragma unroll
            for (int jb = 0; jb < 4; jb++) {
                uint32_t bf[4];
                ldsm4(bf, st + HSUB_BYTES + offB[jb][kk]);
                #pragma unroll
                for (int half = 0; half < 2; half++) {
                    const int nt = 2 * jb + half;
                    mma16816h(acc[0][nt], a[0], bf + 2 * half);
                    mma16816h(acc[1][nt], a[1], bf + 2 * half);
                }
            }
        }
    }

    const int r0 = bm + wm + (lane >> 2);
    const int cb0 = bn + wn + (lane & 3) * 2;
    #pragma unroll
    for (int mt = 0; mt < 2; mt++)
        #pragma unroll
        for (int nt = 0; nt < 8; nt++) {
            const int col = cb0 + nt * 8;
            const float bx = bias[col], by = bias[col + 1];
            #pragma unroll
            for (int half = 0; half < 2; half++) {
                const int row = r0 + mt * 16 + half * 8;
                float vx = acc[mt][nt][half * 2 + 0] + bx;
                float vy = acc[mt][nt][half * 2 + 1] + by;
                const size_t idx = (size_t)row * Dd + col;
                float2 pp = *(const float2*)(ux + idx);
                vx = pp.x * (1.0f / (1.0f + __expf(-vx)));
                vy = pp.y * (1.0f / (1.0f + __expf(-vy)));
                if (epi == 1) {
                    float2 o; o.x = vx; o.y = vy;
                    *(float2*)(C + idx) = o;
                } else {
                    __nv_bfloat16 h0 = __float2bfloat16_rn(vx);
                    __nv_bfloat16 h1 = __float2bfloat16_rn(vy);
                    __nv_bfloat162 hh2; hh2.x = h0; hh2.y = h1;
                    *(__nv_bfloat162*)(v0 + idx) = hh2;
                    __nv_bfloat162 ll;
                    ll.x = __float2bfloat16_rn(vx - __bfloat162float(h0));
                    ll.y = __float2bfloat16_rn(vy - __bfloat162float(h1));
                    *(__nv_bfloat162*)(v1 + idx) = ll;
                }
            }
        }
}

// ================== split / merged transpose-split ================================
__global__ void split4_k(const float* __restrict__ s,
                         __nv_bfloat16* __restrict__ b0, __nv_bfloat16* __restrict__ b1, int n4)
{
    int i = blockIdx.x * blockDim.x + threadIdx.x;
    if (i >= n4) return;
    float4 v = ((const float4*)s)[i];
    const float* vv = (const float*)&v;
    #pragma unroll
    for (int p = 0; p < 4; p += 2) {
        __nv_bfloat16 h0 = __float2bfloat16_rn(vv[p]);
        __nv_bfloat16 h1 = __float2bfloat16_rn(vv[p + 1]);
        __nv_bfloat162 hh; hh.x = h0; hh.y = h1;
        *(__nv_bfloat162*)(b0 + (size_t)i * 4 + p) = hh;
        __nv_bfloat162 ll;
        ll.x = __float2bfloat16_rn(vv[p]     - __bfloat162float(h0));
        ll.y = __float2bfloat16_rn(vv[p + 1] - __bfloat162float(h1));
        *(__nv_bfloat162*)(b1 + (size_t)i * 4 + p) = ll;
    }
}

__global__ void tsplit_all_k(const float* __restrict__ ipw, const float* __restrict__ gw,
                             const float* __restrict__ opw,
                             __nv_bfloat16* __restrict__ T0, __nv_bfloat16* __restrict__ T1,
                             __half* __restrict__ TH)
{
    __shared__ float tile[32][33];
    int gn0 = blockIdx.x * 32;
    int k0  = blockIdx.y * 32;
    int tx = threadIdx.x, ty = threadIdx.y;

    const float* W; int N; int nbase;
    if (gn0 < PROJ_N)            { W = ipw;                  N = PROJ_N; nbase = gn0; }
    else if (gn0 < PROJ_N + Dd)  { W = gw;                   N = Dd;     nbase = gn0 - PROJ_N; }
    else if (gn0 < PROJ_N + 2*Dd){ W = gw + (size_t)Dd * Dd; N = Dd;     nbase = gn0 - PROJ_N - Dd; }
    else                         { W = opw;                  N = Dd;     nbase = gn0 - PROJ_N - 2*Dd; }

    #pragma unroll
    for (int j = 0; j < 32; j += 8)
        tile[ty + j][tx] = W[(size_t)(k0 + ty + j) * N + nbase + tx];
    __syncthreads();
    #pragma unroll
    for (int j = 0; j < 32; j += 8) {
        int n = gn0 + ty + j, k = k0 + tx;
        float v = tile[tx][ty + j];
        __nv_bfloat16 h = __float2bfloat16_rn(v);
        size_t o = (size_t)n * KDIM + k;
        T0[o] = h;
        T1[o] = __float2bfloat16_rn(v - __bfloat162float(h));
        if (n >= PROJ_N && n < PROJ_N + 2 * Dd)
            TH[(size_t)(n - PROJ_N) * KDIM + k] = __float2half(v);
    }
}

// ================== filter ========================================================
__device__ __forceinline__ float gelu_exact(float x) {
    return 0.5f * x * (1.0f + erff(x * 0.70710678118654752f));
}

__global__ void filter_k(const float* __restrict__ freqs,
                         const float* __restrict__ w1, const float* __restrict__ b1,
                         const float* __restrict__ w2, const float* __restrict__ b2,
                         const float* __restrict__ w3, const float* __restrict__ b3,
                         const float* __restrict__ decay, int ord,
                         float* __restrict__ h)
{
    const int n   = blockIdx.x;
    const int tid = threadIdx.x;
    const float t = (float)n / (float)(Ls - 1);
    __shared__ float h1s[64];
    __shared__ float h2s[64];
    float enc[7];
    const float* f = freqs + ord * 3;
    #pragma unroll
    for (int j = 0; j < 3; j++) {
        float ang = 6.283185307179586f * f[j] * t;
        enc[j] = sinf(ang); enc[3 + j] = cosf(ang);
    }
    enc[6] = t;
    if (tid < 64) {
        float s = b1[ord * 64 + tid];
        #pragma unroll
        for (int k = 0; k < 7; k++) s += enc[k] * w1[(ord * 7 + k) * 64 + tid];
        h1s[tid] = gelu_exact(s);
    }
    __syncthreads();
    if (tid < 64) {
        float s = b2[ord * 64 + tid];
        for (int k = 0; k < 64; k++) s += h1s[k] * w2[(ord * 64 + k) * 64 + tid];
        h2s[tid] = gelu_exact(s);
    }
    __syncthreads();
    for (int d = tid; d < Dd; d += blockDim.x) {
        float s = b3[(size_t)ord * Dd + d];
        for (int k = 0; k < 64; k++) s += h2s[k] * w3[((size_t)ord * 64 + k) * Dd + d];
        float wind = expf(-fabsf(decay[(size_t)ord * Dd + d]) * t * (float)Ls);
        h[(size_t)n * Dd + d] = s * wind;
    }
}

// ================== merged convlong + conv3, fused ux = u*xc, fp16 xc =============
#define CT 32
__global__ void __launch_bounds__(128) convs_k(
    const float* __restrict__ vin, int vstride,
    const float* __restrict__ hflt,
    float* __restrict__ ux,
    const float* __restrict__ proj, int off,
    const float* __restrict__ w, const float* __restrict__ cb,
    __half* __restrict__ oh)
{
    __shared__ float vs[CT + TAPS - 1][128];
    const int tx = threadIdx.x;
    const int d  = blockIdx.x * 128 + tx;
    const int t0 = blockIdx.y * CT;
    const int b  = blockIdx.z;

    #pragma unroll 5
    for (int r = 0; r < CT + TAPS - 1; r++) {
        int t = t0 - (TAPS - 1) + r;
        vs[r][tx] = (t >= 0) ? vin[((size_t)b * Ls + t) * vstride + d] : 0.f;
    }
    __syncthreads();

    float acc[CT];
    #pragma unroll
    for (int j = 0; j < CT; j++) acc[j] = 0.f;
    #pragma unroll
    for (int l0 = 0; l0 < TAPS; l0 += 16) {
        float hr[16];
        #pragma unroll
        for (int l = 0; l < 16; l++) hr[l] = hflt[(size_t)(l0 + l) * Dd + d];
        float vv[CT + 15];
        #pragma unroll
        for (int p = 0; p < CT + 15; p++) vv[p] = vs[(TAPS - 1 - 15) - l0 + p][tx];
        #pragma unroll
        for (int l = 0; l < 16; l++)
            #pragma unroll
            for (int j = 0; j < CT; j++)
                acc[j] = fmaf(vv[15 + j - l], hr[l], acc[j]);
    }

    const float wl = w[d], wc = w[Dd + d], wr = w[2 * Dd + d], cbv = cb[d];
    const float* pbase = proj + ((size_t)b * Ls + t0) * PROJ_N + off + d;
    #pragma unroll 4
    for (int j = 0; j < CT; j++) {
        int t = t0 + j;
        const float* p = pbase + (size_t)j * PROJ_N;
        float s = cbv + p[0] * wc;
        if (t > 0)      s += p[-PROJ_N] * wl;
        if (t < Ls - 1) s += p[PROJ_N]  * wr;
        size_t idx = ((size_t)b * Ls + t) * Dd + d;
        ux[idx] = acc[j] * s;
        oh[idx] = __float2half(s);
    }
}

// =================================================================================
extern "C" void kernel_launch(void* const* d_in, const int* in_sizes, int n_in,
                              void* d_out, int out_size)
{
    const float* x    = (const float*)d_in[0];
    const float* ipw  = (const float*)d_in[1];
    const float* ipb  = (const float*)d_in[2];
    const float* opw  = (const float*)d_in[3];
    const float* opb  = (const float*)d_in[4];
    const float* fre  = (const float*)d_in[5];
    const float* w1   = (const float*)d_in[6];
    const float* b1   = (const float*)d_in[7];
    const float* w2   = (const float*)d_in[8];
    const float* b2   = (const float*)d_in[9];
    const float* w3   = (const float*)d_in[10];
    const float* b3   = (const float*)d_in[11];
    const float* dec  = (const float*)d_in[12];
    const float* cw   = (const float*)d_in[13];
    const float* cb   = (const float*)d_in[14];
    const float* gw   = (const float*)d_in[15];
    const float* gb   = (const float*)d_in[16];
    float* out = (float*)d_out;

    float *p_proj, *p_h, *p_v, *p_ux;
    __nv_bfloat16 *p_w0, *p_w1, *p_a0, *p_a1, *p_v0, *p_v1;
    __half *p_wh, *p_ch;
    cudaGetSymbolAddress((void**)&p_proj, g_proj);
    cudaGetSymbolAddress((void**)&p_h,    g_h);
    cudaGetSymbolAddress((void**)&p_v,    g_v);
    cudaGetSymbolAddress((void**)&p_ux,   g_ux);
    cudaGetSymbolAddress((void**)&p_w0,   g_w0);
    cudaGetSymbolAddress((void**)&p_w1,   g_w1);
    cudaGetSymbolAddress((void**)&p_wh,   g_wh);
    cudaGetSymbolAddress((void**)&p_a0,   g_a0);
    cudaGetSymbolAddress((void**)&p_a1,   g_a1);
    cudaGetSymbolAddress((void**)&p_ch,   g_ch);
    cudaGetSymbolAddress((void**)&p_v0,   g_v0);
    cudaGetSymbolAddress((void**)&p_v1,   g_v1);

    cudaFuncSetAttribute(gemm_bf16x3_k, cudaFuncAttributeMaxDynamicSharedMemorySize, GEMM_SMEM);
    cudaFuncSetAttribute(gemm_f16_k,    cudaFuncAttributeMaxDynamicSharedMemorySize, HGEMM_SMEM);

    // split x into bf16 comps
    {
        int n4 = Mrows * KDIM / 4;
        split4_k<<<(n4 + 255) / 256, 256>>>(x, p_a0, p_a1, n4);
    }
    // transpose-split ALL weights (bf16 splits) + fp16 gate weights
    {
        dim3 b(32, 8);
        tsplit_all_k<<<dim3(WROWS / 32, KDIM / 32), b>>>(ipw, gw, opw, p_w0, p_w1, p_wh);
    }

    // 1) proj = x @ in_proj_w + b  (bf16x3)
    gemm_bf16x3_k<<<dim3(PROJ_N / 128, Mrows / 128), 256, GEMM_SMEM>>>(
        p_a0, p_a1, p_w0, p_w1, ipb, p_proj, PROJ_N, KDIM);

    for (int i = 0; i < ORD; i++) {
        filter_k<<<TAPS, 256>>>(fre, w1, b1, w2, b2, w3, b3, dec, i, p_h);

        const float* vin = (i == 0) ? p_proj : p_v;
        int vstride      = (i == 0) ? PROJ_N : Dd;
        dim3 gc(Dd / 128, Ls / CT, Bb);
        convs_k<<<gc, 128>>>(vin, vstride, p_h, p_ux,
                             p_proj, (i + 1) * Dd,
                             cw + (size_t)i * 3 * Dd, cb + (size_t)i * Dd,
                             p_ch);

        // gate GEMM (fp16 single-pass): v = ux * sigmoid(xc@gw + gb)
        gemm_f16_k<<<dim3(Dd / 128, Mrows / 128), 256, HGEMM_SMEM>>>(
            p_ch, p_wh + (size_t)i * Dd * KDIM,
            gb + (size_t)i * Dd, p_v, (i == 0) ? 1 : 2,
            p_ux, p_v0, p_v1);
    }

    // 3) out = v @ out_proj_w + b  (bf16x3)
    gemm_bf16x3_k<<<dim3(Dd / 128, Mrows / 128), 256, GEMM_SMEM>>>(
        p_v0, p_v1,
        p_w0 + (size_t)(PROJ_N + 2 * Dd) * KDIM,
        p_w1 + (size_t)(PROJ_N + 2 * Dd) * KDIM,
        opb, out, Dd, KDIM);
}

// round 12
// speedup vs baseline: 1.3451x; 1.1386x over previous
#include <cuda_runtime.h>
#include <cuda_bf16.h>
#include <cuda_fp16.h>
#include <math.h>
#include <stdint.h>

// Problem constants
#define Bb     2
#define Ls     4096
#define Dd     1024
#define ORD    2
#define PROJ_N (3*Dd)
#define TAPS   64
#define Mrows  (Bb*Ls)
#define KDIM   1024
#define WROWS  (PROJ_N + 3*Dd)

// ---------------- scratch (device globals) -------------------------------------
__device__ float g_proj[(size_t)Mrows*PROJ_N];
__device__ float g_h[(size_t)TAPS*Dd];
__device__ float g_v[(size_t)Mrows*Dd];
__device__ float g_ux[(size_t)Mrows*Dd];            // u * xc (pre-multiplied)
__device__ __half        g_ah[(size_t)Mrows*KDIM];  // fp16 x
__device__ __half        g_wih[(size_t)PROJ_N*KDIM]; // fp16 in_proj W hi (transposed)
__device__ __half        g_wil[(size_t)PROJ_N*KDIM]; // fp16 in_proj W lo
__device__ __half        g_wh[(size_t)2*Dd*KDIM];   // fp16 gate weights (transposed)
__device__ __nv_bfloat16 g_wo0[(size_t)Dd*KDIM];    // bf16 out_proj hi
__device__ __nv_bfloat16 g_wo1[(size_t)Dd*KDIM];    // bf16 out_proj lo
__device__ __half        g_ch[(size_t)Mrows*KDIM];  // fp16 xc
__device__ __nv_bfloat16 g_v0[(size_t)Mrows*KDIM];
__device__ __nv_bfloat16 g_v1[(size_t)Mrows*KDIM];

// ---------------- helpers -------------------------------------------------------
__device__ __forceinline__ uint32_t smem_u32(const void* p) {
    uint32_t a;
    asm("{ .reg .u64 t; cvta.to.shared.u64 t, %1; cvt.u32.u64 %0, t; }" : "=r"(a) : "l"(p));
    return a;
}
__device__ __forceinline__ void ldsm4(uint32_t* r, uint32_t addr) {
    asm volatile("ldmatrix.sync.aligned.m8n8.x4.shared.b16 {%0,%1,%2,%3}, [%4];"
                 : "=r"(r[0]), "=r"(r[1]), "=r"(r[2]), "=r"(r[3]) : "r"(addr));
}
__device__ __forceinline__ void mma16816(float* c, const uint32_t* a, const uint32_t* b) {
    asm volatile(
        "mma.sync.aligned.m16n8k16.row.col.f32.bf16.bf16.f32 "
        "{%0,%1,%2,%3}, {%4,%5,%6,%7}, {%8,%9}, {%0,%1,%2,%3};"
        : "+f"(c[0]), "+f"(c[1]), "+f"(c[2]), "+f"(c[3])
        : "r"(a[0]), "r"(a[1]), "r"(a[2]), "r"(a[3]), "r"(b[0]), "r"(b[1]));
}
__device__ __forceinline__ void mma16816h(float* c, const uint32_t* a, const uint32_t* b) {
    asm volatile(
        "mma.sync.aligned.m16n8k16.row.col.f32.f16.f16.f32 "
        "{%0,%1,%2,%3}, {%4,%5,%6,%7}, {%8,%9}, {%0,%1,%2,%3};"
        : "+f"(c[0]), "+f"(c[1]), "+f"(c[2]), "+f"(c[3])
        : "r"(a[0]), "r"(a[1]), "r"(a[2]), "r"(a[3]), "r"(b[0]), "r"(b[1]));
}

#define STAGES      3
#define CHUNK_K     32
#define SUB_BYTES   8192

// ================== bf16x3 GEMM (out_proj) =======================================
#define STAGE3_BYTES (4*SUB_BYTES)
#define GEMM3_SMEM   (STAGES*STAGE3_BYTES)

__global__ void __launch_bounds__(256, 2) gemm_bf16x3_k(
    const __nv_bfloat16* __restrict__ A0, const __nv_bfloat16* __restrict__ A1,
    const __nv_bfloat16* __restrict__ B0, const __nv_bfloat16* __restrict__ B1,
    const float* __restrict__ bias, float* __restrict__ C, int ldc)
{
    extern __shared__ char smem[];
    const uint32_t stg = smem_u32(smem);
    const int tid = threadIdx.x, wid = tid >> 5, lane = tid & 31;
    const int bm = blockIdx.y * 128, bn = blockIdx.x * 128;
    const int wm = (wid & 3) * 32, wn = (wid >> 2) * 64;
    const int nchunk = KDIM / CHUNK_K;

    const __nv_bfloat16* sA0 = A0 + (size_t)bm * KDIM;
    const __nv_bfloat16* sA1 = A1 + (size_t)bm * KDIM;
    const __nv_bfloat16* sB0 = B0 + (size_t)bn * KDIM;
    const __nv_bfloat16* sB1 = B1 + (size_t)bn * KDIM;

    auto fill = [&](int chunk, int stage) {
        const uint32_t st = stg + stage * STAGE3_BYTES;
        const int k0 = chunk * CHUNK_K;
        const __nv_bfloat16* gs[4] = { sA0, sA1, sB0, sB1 };
        #pragma unroll
        for (int sub = 0; sub < 4; sub++) {
            const __nv_bfloat16* g = gs[sub] + k0;
            const uint32_t db = st + sub * SUB_BYTES;
            #pragma unroll
            for (int i = 0; i < 2; i++) {
                int idx = tid + i * 256;
                int row = idx >> 2, cs = idx & 3;
                const void* gp = g + (size_t)row * KDIM + cs * 8;
                uint32_t dp = db + row * 64 + ((cs ^ ((row >> 1) & 3)) << 4);
                asm volatile("cp.async.cg.shared.global [%0], [%1], 16;"
                             :: "r"(dp), "l"(gp) : "memory");
            }
        }
        asm volatile("cp.async.commit_group;" ::: "memory");
    };

    fill(0, 0);
    fill(1, 1);

    float acc[2][8][4];
    #pragma unroll
    for (int i = 0; i < 2; i++)
        #pragma unroll
        for (int j = 0; j < 8; j++)
            #pragma unroll
            for (int p = 0; p < 4; p++) acc[i][j][p] = 0.f;

    uint32_t offA[2][2], offB[4][2];
    #pragma unroll
    for (int mt = 0; mt < 2; mt++) {
        int row = wm + mt * 16 + (lane & 15);
        #pragma unroll
        for (int kk = 0; kk < 2; kk++) {
            int cs = kk * 2 + (lane >> 4);
            offA[mt][kk] = row * 64 + ((cs ^ ((row >> 1) & 3)) << 4);
        }
    }
    #pragma unroll
    for (int jb = 0; jb < 4; jb++) {
        int n = wn + jb * 16 + ((lane >> 4) << 3) + (lane & 7);
        #pragma unroll
        for (int kk = 0; kk < 2; kk++) {
            int cs = kk * 2 + ((lane >> 3) & 1);
            offB[jb][kk] = n * 64 + ((cs ^ ((n >> 1) & 3)) << 4);
        }
    }

    for (int c = 0; c < nchunk; c++) {
        const int s = c % STAGES;
        asm volatile("cp.async.wait_group 1;" ::: "memory");
        __syncthreads();

        const int nc = c + STAGES - 1;
        if (nc < nchunk) fill(nc, nc % STAGES);

        const uint32_t st = stg + s * STAGE3_BYTES;
        #pragma unroll
        for (int kk = 0; kk < 2; kk++) {
            uint32_t ah[2][4], al[2][4];
            #pragma unroll
            for (int mt = 0; mt < 2; mt++) {
                ldsm4(ah[mt], st + offA[mt][kk]);
                ldsm4(al[mt], st + SUB_BYTES + offA[mt][kk]);
            }
            #pragma unroll
            for (int jb = 0; jb < 4; jb++) {
                uint32_t bh[4], bl[4];
                ldsm4(bh, st + 2 * SUB_BYTES + offB[jb][kk]);
                ldsm4(bl, st + 3 * SUB_BYTES + offB[jb][kk]);
                #pragma unroll
                for (int half = 0; half < 2; half++) {
                    const int nt = 2 * jb + half;
                    #pragma unroll
                    for (int mt = 0; mt < 2; mt++) {
                        mma16816(acc[mt][nt], ah[mt], bh + 2 * half);
                        mma16816(acc[mt][nt], ah[mt], bl + 2 * half);
                        mma16816(acc[mt][nt], al[mt], bh + 2 * half);
                    }
                }
            }
        }
    }

    const int r0 = bm + wm + (lane >> 2);
    const int cb0 = bn + wn + (lane & 3) * 2;
    #pragma unroll
    for (int mt = 0; mt < 2; mt++)
        #pragma unroll
        for (int nt = 0; nt < 8; nt++) {
            const int col = cb0 + nt * 8;
            const float bx = bias[col], by = bias[col + 1];
            #pragma unroll
            for (int half = 0; half < 2; half++) {
                const int row = r0 + mt * 16 + half * 8;
                float2 o;
                o.x = acc[mt][nt][half * 2 + 0] + bx;
                o.y = acc[mt][nt][half * 2 + 1] + by;
                *(float2*)(C + (size_t)row * ldc + col) = o;
            }
        }
}

// ================== fp16 A-single x W-2comp GEMM (in_proj) =======================
#define STAGEW2_BYTES (3*SUB_BYTES)
#define GEMMW2_SMEM   (STAGES*STAGEW2_BYTES)

__global__ void __launch_bounds__(256, 2) gemm_f16w2_k(
    const __half* __restrict__ A,
    const __half* __restrict__ B0, const __half* __restrict__ B1,
    const float* __restrict__ bias, float* __restrict__ C, int ldc)
{
    extern __shared__ char smem[];
    const uint32_t stg = smem_u32(smem);
    const int tid = threadIdx.x, wid = tid >> 5, lane = tid & 31;
    const int bm = blockIdx.y * 128, bn = blockIdx.x * 128;
    const int wm = (wid & 3) * 32, wn = (wid >> 2) * 64;
    const int nchunk = KDIM / CHUNK_K;

    const __half* sA  = A  + (size_t)bm * KDIM;
    const __half* sB0 = B0 + (size_t)bn * KDIM;
    const __half* sB1 = B1 + (size_t)bn * KDIM;

    auto fill = [&](int chunk, int stage) {
        const uint32_t st = stg + stage * STAGEW2_BYTES;
        const int k0 = chunk * CHUNK_K;
        const __half* gs[3] = { sA, sB0, sB1 };
        #pragma unroll
        for (int sub = 0; sub < 3; sub++) {
            const __half* g = gs[sub] + k0;
            const uint32_t db = st + sub * SUB_BYTES;
            #pragma unroll
            for (int i = 0; i < 2; i++) {
                int idx = tid + i * 256;
                int row = idx >> 2, cs = idx & 3;
                const void* gp = g + (size_t)row * KDIM + cs * 8;
                uint32_t dp = db + row * 64 + ((cs ^ ((row >> 1) & 3)) << 4);
                asm volatile("cp.async.cg.shared.global [%0], [%1], 16;"
                             :: "r"(dp), "l"(gp) : "memory");
            }
        }
        asm volatile("cp.async.commit_group;" ::: "memory");
    };

    fill(0, 0);
    fill(1, 1);

    float acc[2][8][4];
    #pragma unroll
    for (int i = 0; i < 2; i++)
        #pragma unroll
        for (int j = 0; j < 8; j++)
            #pragma unroll
            for (int p = 0; p < 4; p++) acc[i][j][p] = 0.f;

    uint32_t offA[2][2], offB[4][2];
    #pragma unroll
    for (int mt = 0; mt < 2; mt++) {
        int row = wm + mt * 16 + (lane & 15);
        #pragma unroll
        for (int kk = 0; kk < 2; kk++) {
            int cs = kk * 2 + (lane >> 4);
            offA[mt][kk] = row * 64 + ((cs ^ ((row >> 1) & 3)) << 4);
        }
    }
    #pragma unroll
    for (int jb = 0; jb < 4; jb++) {
        int n = wn + jb * 16 + ((lane >> 4) << 3) + (lane & 7);
        #pragma unroll
        for (int kk = 0; kk < 2; kk++) {
            int cs = kk * 2 + ((lane >> 3) & 1);
            offB[jb][kk] = n * 64 + ((cs ^ ((n >> 1) & 3)) << 4);
        }
    }

    for (int c = 0; c < nchunk; c++) {
        const int s = c % STAGES;
        asm volatile("cp.async.wait_group 1;" ::: "memory");
        __syncthreads();

        const int nc = c + STAGES - 1;
        if (nc < nchunk) fill(nc, nc % STAGES);

        const uint32_t st = stg + s * STAGEW2_BYTES;
        #pragma unroll
        for (int kk = 0; kk < 2; kk++) {
            uint32_t a[2][4];
            ldsm4(a[0], st + offA[0][kk]);
            ldsm4(a[1], st + offA[1][kk]);
            #pragma unroll
            for (int jb = 0; jb < 4; jb++) {
                uint32_t bh[4], bl[4];
                ldsm4(bh, st + SUB_BYTES + offB[jb][kk]);
                ldsm4(bl, st + 2 * SUB_BYTES + offB[jb][kk]);
                #pragma unroll
                for (int half = 0; half < 2; half++) {
                    const int nt = 2 * jb + half;
                    #pragma unroll
                    for (int mt = 0; mt < 2; mt++) {
                        mma16816h(acc[mt][nt], a[mt], bh + 2 * half);
                        mma16816h(acc[mt][nt], a[mt], bl + 2 * half);
                    }
                }
            }
        }
    }

    const int r0 = bm + wm + (lane >> 2);
    const int cb0 = bn + wn + (lane & 3) * 2;
    #pragma unroll
    for (int mt = 0; mt < 2; mt++)
        #pragma unroll
        for (int nt = 0; nt < 8; nt++) {
            const int col = cb0 + nt * 8;
            const float bx = bias[col], by = bias[col + 1];
            #pragma unroll
            for (int half = 0; half < 2; half++) {
                const int row = r0 + mt * 16 + half * 8;
                float2 o;
                o.x = acc[mt][nt][half * 2 + 0] + bx;
                o.y = acc[mt][nt][half * 2 + 1] + by;
                *(float2*)(C + (size_t)row * ldc + col) = o;
            }
        }
}

// ================== fp16 single-pass GEMM (gate GEMMs) ===========================
#define HSTAGE_BYTES (2*SUB_BYTES)
#define HGEMM_SMEM   (STAGES*HSTAGE_BYTES)

__global__ void __launch_bounds__(256, 2) gemm_f16_k(
    const __half* __restrict__ A, const __half* __restrict__ B,
    const float* __restrict__ bias, float* __restrict__ C, int epi,
    const float* __restrict__ ux,
    __nv_bfloat16* __restrict__ v0, __nv_bfloat16* __restrict__ v1)
{
    extern __shared__ char smem[];
    const uint32_t stg = smem_u32(smem);
    const int tid = threadIdx.x, wid = tid >> 5, lane = tid & 31;
    const int bm = blockIdx.y * 128, bn = blockIdx.x * 128;
    const int wm = (wid & 3) * 32, wn = (wid >> 2) * 64;
    const int nchunk = KDIM / CHUNK_K;

    const __half* sA = A + (size_t)bm * KDIM;
    const __half* sB = B + (size_t)bn * KDIM;

    auto fill = [&](int chunk, int stage) {
        const uint32_t st = stg + stage * HSTAGE_BYTES;
        const int k0 = chunk * CHUNK_K;
        const __half* gs[2] = { sA, sB };
        #pragma unroll
        for (int sub = 0; sub < 2; sub++) {
            const __half* g = gs[sub] + k0;
            const uint32_t db = st + sub * SUB_BYTES;
            #pragma unroll
            for (int i = 0; i < 2; i++) {
                int idx = tid + i * 256;
                int row = idx >> 2, cs = idx & 3;
                const void* gp = g + (size_t)row * KDIM + cs * 8;
                uint32_t dp = db + row * 64 + ((cs ^ ((row >> 1) & 3)) << 4);
                asm volatile("cp.async.cg.shared.global [%0], [%1], 16;"
                             :: "r"(dp), "l"(gp) : "memory");
            }
        }
        asm volatile("cp.async.commit_group;" ::: "memory");
    };

    fill(0, 0);
    fill(1, 1);

    float acc[2][8][4];
    #pragma unroll
    for (int i = 0; i < 2; i++)
        #pragma unroll
        for (int j = 0; j < 8; j++)
            #pragma unroll
            for (int p = 0; p < 4; p++) acc[i][j][p] = 0.f;

    uint32_t offA[2][2], offB[4][2];
    #pragma unroll
    for (int mt = 0; mt < 2; mt++) {
        int row = wm + mt * 16 + (lane & 15);
        #pragma unroll
        for (int kk = 0; kk < 2; kk++) {
            int cs = kk * 2 + (lane >> 4);
            offA[mt][kk] = row * 64 + ((cs ^ ((row >> 1) & 3)) << 4);
        }
    }
    #pragma unroll
    for (int jb = 0; jb < 4; jb++) {
        int n = wn + jb * 16 + ((lane >> 4) << 3) + (lane & 7);
        #pragma unroll
        for (int kk = 0; kk < 2; kk++) {
            int cs = kk * 2 + ((lane >> 3) & 1);
            offB[jb][kk] = n * 64 + ((cs ^ ((n >> 1) & 3)) << 4);
        }
    }

    for (int c = 0; c < nchunk; c++) {
        const int s = c % STAGES;
        asm volatile("cp.async.wait_group 1;" ::: "memory");
        __syncthreads();

        const int nc = c + STAGES - 1;
        if (nc < nchunk) fill(nc, nc % STAGES);

        const uint32_t st = stg + s * HSTAGE_BYTES;
        #pragma unroll
        for (int kk = 0; kk < 2; kk++) {
            uint32_t a[2][4];
            ldsm4(a[0], st + offA[0][kk]);
            ldsm4(a[1], st + offA[1][kk]);
            #pragma unroll
            for (int jb = 0; jb < 4; jb++) {
                uint32_t bf[4];
                ldsm4(bf, st + SUB_BYTES + offB[jb][kk]);
                #pragma unroll
                for (int half = 0; half < 2; half++) {
                    const int nt = 2 * jb + half;
                    mma16816h(acc[0][nt], a[0], bf + 2 * half);
                    mma16816h(acc[1][nt], a[1], bf + 2 * half);
                }
            }
        }
    }

    const int r0 = bm + wm + (lane >> 2);
    const int cb0 = bn + wn + (lane & 3) * 2;
    #pragma unroll
    for (int mt = 0; mt < 2; mt++)
        #pragma unroll
        for (int nt = 0; nt < 8; nt++) {
            const int col = cb0 + nt * 8;
            const float bx = bias[col], by = bias[col + 1];
            #pragma unroll
            for (int half = 0; half < 2; half++) {
                const int row = r0 + mt * 16 + half * 8;
                float vx = acc[mt][nt][half * 2 + 0] + bx;
                float vy = acc[mt][nt][half * 2 + 1] + by;
                const size_t idx = (size_t)row * Dd + col;
                float2 pp = *(const float2*)(ux + idx);
                vx = pp.x * (1.0f / (1.0f + __expf(-vx)));
                vy = pp.y * (1.0f / (1.0f + __expf(-vy)));
                if (epi == 1) {
                    float2 o; o.x = vx; o.y = vy;
                    *(float2*)(C + idx) = o;
                } else {
                    __nv_bfloat16 h0 = __float2bfloat16_rn(vx);
                    __nv_bfloat16 h1 = __float2bfloat16_rn(vy);
                    __nv_bfloat162 hh2; hh2.x = h0; hh2.y = h1;
                    *(__nv_bfloat162*)(v0 + idx) = hh2;
                    __nv_bfloat162 ll;
                    ll.x = __float2bfloat16_rn(vx - __bfloat162float(h0));
                    ll.y = __float2bfloat16_rn(vy - __bfloat162float(h1));
                    *(__nv_bfloat162*)(v1 + idx) = ll;
                }
            }
        }
}

// ================== quant / transpose-split ======================================
__global__ void quantx_k(const float* __restrict__ s, __half* __restrict__ o, int n4) {
    int i = blockIdx.x * blockDim.x + threadIdx.x;
    if (i >= n4) return;
    float4 v = ((const float4*)s)[i];
    __half2 h0; h0.x = __float2half(v.x); h0.y = __float2half(v.y);
    __half2 h1; h1.x = __float2half(v.z); h1.y = __float2half(v.w);
    *(__half2*)(o + (size_t)i * 4)     = h0;
    *(__half2*)(o + (size_t)i * 4 + 2) = h1;
}

__global__ void tsplit_all_k(const float* __restrict__ ipw, const float* __restrict__ gw,
                             const float* __restrict__ opw,
                             __half* __restrict__ WIH, __half* __restrict__ WIL,
                             __half* __restrict__ WG,
                             __nv_bfloat16* __restrict__ WO0, __nv_bfloat16* __restrict__ WO1)
{
    __shared__ float tile[32][33];
    int gn0 = blockIdx.x * 32;
    int k0  = blockIdx.y * 32;
    int tx = threadIdx.x, ty = threadIdx.y;   // 32 x 8

    const float* W; int N; int nbase;
    if (gn0 < PROJ_N)            { W = ipw;                  N = PROJ_N; nbase = gn0; }
    else if (gn0 < PROJ_N + Dd)  { W = gw;                   N = Dd;     nbase = gn0 - PROJ_N; }
    else if (gn0 < PROJ_N + 2*Dd){ W = gw + (size_t)Dd * Dd; N = Dd;     nbase = gn0 - PROJ_N - Dd; }
    else                         { W = opw;                  N = Dd;     nbase = gn0 - PROJ_N - 2*Dd; }

    #pragma unroll
    for (int j = 0; j < 32; j += 8)
        tile[ty + j][tx] = W[(size_t)(k0 + ty + j) * N + nbase + tx];
    __syncthreads();
    #pragma unroll
    for (int j = 0; j < 32; j += 8) {
        int n = gn0 + ty + j, k = k0 + tx;
        float v = tile[tx][ty + j];
        if (n < PROJ_N) {
            __half h = __float2half(v);
            size_t o = (size_t)n * KDIM + k;
            WIH[o] = h;
            WIL[o] = __float2half(v - __half2float(h));
        } else if (n < PROJ_N + 2 * Dd) {
            WG[(size_t)(n - PROJ_N) * KDIM + k] = __float2half(v);
        } else {
            __nv_bfloat16 h = __float2bfloat16_rn(v);
            size_t o = (size_t)(n - PROJ_N - 2 * Dd) * KDIM + k;
            WO0[o] = h;
            WO1[o] = __float2bfloat16_rn(v - __bfloat162float(h));
        }
    }
}

// ================== filter ========================================================
__device__ __forceinline__ float gelu_exact(float x) {
    return 0.5f * x * (1.0f + erff(x * 0.70710678118654752f));
}

__global__ void filter_k(const float* __restrict__ freqs,
                         const float* __restrict__ w1, const float* __restrict__ b1,
                         const float* __restrict__ w2, const float* __restrict__ b2,
                         const float* __restrict__ w3, const float* __restrict__ b3,
                         const float* __restrict__ decay, int ord,
                         float* __restrict__ h)
{
    const int n   = blockIdx.x;
    const int tid = threadIdx.x;
    const float t = (float)n / (float)(Ls - 1);
    __shared__ float h1s[64];
    __shared__ float h2s[64];
    float enc[7];
    const float* f = freqs + ord * 3;
    #pragma unroll
    for (int j = 0; j < 3; j++) {
        float ang = 6.283185307179586f * f[j] * t;
        enc[j] = sinf(ang); enc[3 + j] = cosf(ang);
    }
    enc[6] = t;
    if (tid < 64) {
        float s = b1[ord * 64 + tid];
        #pragma unroll
        for (int k = 0; k < 7; k++) s += enc[k] * w1[(ord * 7 + k) * 64 + tid];
        h1s[tid] = gelu_exact(s);
    }
    __syncthreads();
    if (tid < 64) {
        float s = b2[ord * 64 + tid];
        for (int k = 0; k < 64; k++) s += h1s[k] * w2[(ord * 64 + k) * 64 + tid];
        h2s[tid] = gelu_exact(s);
    }
    __syncthreads();
    for (int d = tid; d < Dd; d += blockDim.x) {
        float s = b3[(size_t)ord * Dd + d];
        for (int k = 0; k < 64; k++) s += h2s[k] * w3[((size_t)ord * 64 + k) * Dd + d];
        float wind = expf(-fabsf(decay[(size_t)ord * Dd + d]) * t * (float)Ls);
        h[(size_t)n * Dd + d] = s * wind;
    }
}

// ================== merged convlong + conv3, fused ux = u*xc, fp16 xc =============
#define CT 32
__global__ void __launch_bounds__(128) convs_k(
    const float* __restrict__ vin, int vstride,
    const float* __restrict__ hflt,
    float* __restrict__ ux,
    const float* __restrict__ proj, int off,
    const float* __restrict__ w, const float* __restrict__ cb,
    __half* __restrict__ oh)
{
    __shared__ float vs[CT + TAPS - 1][128];
    const int tx = threadIdx.x;
    const int d  = blockIdx.x * 128 + tx;
    const int t0 = blockIdx.y * CT;
    const int b  = blockIdx.z;

    #pragma unroll 5
    for (int r = 0; r < CT + TAPS - 1; r++) {
        int t = t0 - (TAPS - 1) + r;
        vs[r][tx] = (t >= 0) ? vin[((size_t)b * Ls + t) * vstride + d] : 0.f;
    }
    __syncthreads();

    float acc[CT];
    #pragma unroll
    for (int j = 0; j < CT; j++) acc[j] = 0.f;
    #pragma unroll
    for (int l0 = 0; l0 < TAPS; l0 += 16) {
        float hr[16];
        #pragma unroll
        for (int l = 0; l < 16; l++) hr[l] = hflt[(size_t)(l0 + l) * Dd + d];
        float vv[CT + 15];
        #pragma unroll
        for (int p = 0; p < CT + 15; p++) vv[p] = vs[(TAPS - 1 - 15) - l0 + p][tx];
        #pragma unroll
        for (int l = 0; l < 16; l++)
            #pragma unroll
            for (int j = 0; j < CT; j++)
                acc[j] = fmaf(vv[15 + j - l], hr[l], acc[j]);
    }

    const float wl = w[d], wc = w[Dd + d], wr = w[2 * Dd + d], cbv = cb[d];
    const float* pbase = proj + ((size_t)b * Ls + t0) * PROJ_N + off + d;
    #pragma unroll 4
    for (int j = 0; j < CT; j++) {
        int t = t0 + j;
        const float* p = pbase + (size_t)j * PROJ_N;
        float s = cbv + p[0] * wc;
        if (t > 0)      s += p[-PROJ_N] * wl;
        if (t < Ls - 1) s += p[PROJ_N]  * wr;
        size_t idx = ((size_t)b * Ls + t) * Dd + d;
        ux[idx] = acc[j] * s;
        oh[idx] = __float2half(s);
    }
}

// =================================================================================
extern "C" void kernel_launch(void* const* d_in, const int* in_sizes, int n_in,
                              void* d_out, int out_size)
{
    const float* x    = (const float*)d_in[0];
    const float* ipw  = (const float*)d_in[1];
    const float* ipb  = (const float*)d_in[2];
    const float* opw  = (const float*)d_in[3];
    const float* opb  = (const float*)d_in[4];
    const float* fre  = (const float*)d_in[5];
    const float* w1   = (const float*)d_in[6];
    const float* b1   = (const float*)d_in[7];
    const float* w2   = (const float*)d_in[8];
    const float* b2   = (const float*)d_in[9];
    const float* w3   = (const float*)d_in[10];
    const float* b3   = (const float*)d_in[11];
    const float* dec  = (const float*)d_in[12];
    const float* cw   = (const float*)d_in[13];
    const float* cb   = (const float*)d_in[14];
    const float* gw   = (const float*)d_in[15];
    const float* gb   = (const float*)d_in[16];
    float* out = (float*)d_out;

    float *p_proj, *p_h, *p_v, *p_ux;
    __half *p_ah, *p_wih, *p_wil, *p_wh, *p_ch;
    __nv_bfloat16 *p_wo0, *p_wo1, *p_v0, *p_v1;
    cudaGetSymbolAddress((void**)&p_proj, g_proj);
    cudaGetSymbolAddress((void**)&p_h,    g_h);
    cudaGetSymbolAddress((void**)&p_v,    g_v);
    cudaGetSymbolAddress((void**)&p_ux,   g_ux);
    cudaGetSymbolAddress((void**)&p_ah,   g_ah);
    cudaGetSymbolAddress((void**)&p_wih,  g_wih);
    cudaGetSymbolAddress((void**)&p_wil,  g_wil);
    cudaGetSymbolAddress((void**)&p_wh,   g_wh);
    cudaGetSymbolAddress((void**)&p_wo0,  g_wo0);
    cudaGetSymbolAddress((void**)&p_wo1,  g_wo1);
    cudaGetSymbolAddress((void**)&p_ch,   g_ch);
    cudaGetSymbolAddress((void**)&p_v0,   g_v0);
    cudaGetSymbolAddress((void**)&p_v1,   g_v1);

    cudaFuncSetAttribute(gemm_bf16x3_k, cudaFuncAttributeMaxDynamicSharedMemorySize, GEMM3_SMEM);
    cudaFuncSetAttribute(gemm_f16w2_k,  cudaFuncAttributeMaxDynamicSharedMemorySize, GEMMW2_SMEM);
    cudaFuncSetAttribute(gemm_f16_k,    cudaFuncAttributeMaxDynamicSharedMemorySize, HGEMM_SMEM);

    // quantize x to fp16
    {
        int n4 = Mrows * KDIM / 4;
        quantx_k<<<(n4 + 255) / 256, 256>>>(x, p_ah, n4);
    }
    // transpose + per-region quantize all weights
    {
        dim3 b(32, 8);
        tsplit_all_k<<<dim3(WROWS / 32, KDIM / 32), b>>>(ipw, gw, opw,
                                                         p_wih, p_wil, p_wh, p_wo0, p_wo1);
    }

    // 1) proj = x @ in_proj_w + b  (fp16 x-single, W-2comp: 2 passes)
    gemm_f16w2_k<<<dim3(PROJ_N / 128, Mrows / 128), 256, GEMMW2_SMEM>>>(
        p_ah, p_wih, p_wil, ipb, p_proj, PROJ_N);

    for (int i = 0; i < ORD; i++) {
        filter_k<<<TAPS, 256>>>(fre, w1, b1, w2, b2, w3, b3, dec, i, p_h);

        const float* vin = (i == 0) ? p_proj : p_v;
        int vstride      = (i == 0) ? PROJ_N : Dd;
        dim3 gc(Dd / 128, Ls / CT, Bb);
        convs_k<<<gc, 128>>>(vin, vstride, p_h, p_ux,
                             p_proj, (i + 1) * Dd,
                             cw + (size_t)i * 3 * Dd, cb + (size_t)i * Dd,
                             p_ch);

        // gate GEMM (fp16 single-pass): v = ux * sigmoid(xc@gw + gb)
        gemm_f16_k<<<dim3(Dd / 128, Mrows / 128), 256, HGEMM_SMEM>>>(
            p_ch, p_wh + (size_t)i * Dd * KDIM,
            gb + (size_t)i * Dd, p_v, (i == 0) ? 1 : 2,
            p_ux, p_v0, p_v1);
    }

    // 3) out = v @ out_proj_w + b  (bf16x3)
    gemm_bf16x3_k<<<dim3(Dd / 128, Mrows / 128), 256, GEMM3_SMEM>>>(
        p_v0, p_v1, p_wo0, p_wo1, opb, out, Dd);
}

// round 15
// speedup vs baseline: 1.4255x; 1.0598x over previous
#include <cuda_runtime.h>
#include <cuda_bf16.h>
#include <cuda_fp16.h>
#include <math.h>
#include <stdint.h>

// Problem constants
#define Bb     2
#define Ls     4096
#define Dd     1024
#define ORD    2
#define PROJ_N (3*Dd)
#define TAPS   64
#define Mrows  (Bb*Ls)
#define KDIM   1024
#define WROWS  (PROJ_N + 3*Dd)

#define VSCALE     256.0f
#define VSCALE_INV (1.0f/256.0f)

// ---------------- scratch (device globals) -------------------------------------
__device__ float g_proj[(size_t)Mrows*PROJ_N];
__device__ float g_h[(size_t)TAPS*Dd];
__device__ float g_v[(size_t)Mrows*Dd];
__device__ float g_ux[(size_t)Mrows*Dd];             // u * xc (pre-multiplied)
__device__ __half g_ah[(size_t)Mrows*KDIM];          // fp16 x
__device__ __half g_wih[(size_t)PROJ_N*KDIM];        // fp16 in_proj W hi (transposed)
__device__ __half g_wil[(size_t)PROJ_N*KDIM];        // fp16 in_proj W lo
__device__ __half g_wh[(size_t)2*Dd*KDIM];           // fp16 gate weights (transposed)
__device__ __half g_woh[(size_t)Dd*KDIM];            // fp16 out_proj W hi
__device__ __half g_wol[(size_t)Dd*KDIM];            // fp16 out_proj W lo
__device__ __half g_ch[(size_t)Mrows*KDIM];          // fp16 xc
__device__ __half g_vh[(size_t)Mrows*KDIM];          // fp16 256*v (scaled to normal range)

// ---------------- helpers -------------------------------------------------------
__device__ __forceinline__ uint32_t smem_u32(const void* p) {
    uint32_t a;
    asm("{ .reg .u64 t; cvta.to.shared.u64 t, %1; cvt.u32.u64 %0, t; }" : "=r"(a) : "l"(p));
    return a;
}
__device__ __forceinline__ void ldsm4(uint32_t* r, uint32_t addr) {
    asm volatile("ldmatrix.sync.aligned.m8n8.x4.shared.b16 {%0,%1,%2,%3}, [%4];"
                 : "=r"(r[0]), "=r"(r[1]), "=r"(r[2]), "=r"(r[3]) : "r"(addr));
}
__device__ __forceinline__ void mma16816h(float* c, const uint32_t* a, const uint32_t* b) {
    asm volatile(
        "mma.sync.aligned.m16n8k16.row.col.f32.f16.f16.f32 "
        "{%0,%1,%2,%3}, {%4,%5,%6,%7}, {%8,%9}, {%0,%1,%2,%3};"
        : "+f"(c[0]), "+f"(c[1]), "+f"(c[2]), "+f"(c[3])
        : "r"(a[0]), "r"(a[1]), "r"(a[2]), "r"(a[3]), "r"(b[0]), "r"(b[1]));
}

#define STAGES      3
#define CHUNK_K     32
#define SUB_BYTES   8192

// ================== fp16 A-single x W-2comp GEMM (in_proj / out_proj) ============
// C = ascale * (A@[B0+B1]^T) + bias
#define STAGEW2_BYTES (3*SUB_BYTES)
#define GEMMW2_SMEM   (STAGES*STAGEW2_BYTES)

__global__ void __launch_bounds__(256, 2) gemm_f16w2_k(
    const __half* __restrict__ A,
    const __half* __restrict__ B0, const __half* __restrict__ B1,
    const float* __restrict__ bias, float* __restrict__ C, int ldc, float ascale)
{
    extern __shared__ char smem[];
    const uint32_t stg = smem_u32(smem);
    const int tid = threadIdx.x, wid = tid >> 5, lane = tid & 31;
    const int bm = blockIdx.y * 128, bn = blockIdx.x * 128;
    const int wm = (wid & 3) * 32, wn = (wid >> 2) * 64;
    const int nchunk = KDIM / CHUNK_K;

    const __half* sA  = A  + (size_t)bm * KDIM;
    const __half* sB0 = B0 + (size_t)bn * KDIM;
    const __half* sB1 = B1 + (size_t)bn * KDIM;

    auto fill = [&](int chunk, int stage) {
        const uint32_t st = stg + stage * STAGEW2_BYTES;
        const int k0 = chunk * CHUNK_K;
        const __half* gs[3] = { sA, sB0, sB1 };
        #pragma unroll
        for (int sub = 0; sub < 3; sub++) {
            const __half* g = gs[sub] + k0;
            const uint32_t db = st + sub * SUB_BYTES;
            #pragma unroll
            for (int i = 0; i < 2; i++) {
                int idx = tid + i * 256;
                int row = idx >> 2, cs = idx & 3;
                const void* gp = g + (size_t)row * KDIM + cs * 8;
                uint32_t dp = db + row * 64 + ((cs ^ ((row >> 1) & 3)) << 4);
                asm volatile("cp.async.cg.shared.global [%0], [%1], 16;"
                             :: "r"(dp), "l"(gp) : "memory");
            }
        }
        asm volatile("cp.async.commit_group;" ::: "memory");
    };

    fill(0, 0);
    fill(1, 1);

    float acc[2][8][4];
    #pragma unroll
    for (int i = 0; i < 2; i++)
        #pragma unroll
        for (int j = 0; j < 8; j++)
            #pragma unroll
            for (int p = 0; p < 4; p++) acc[i][j][p] = 0.f;

    uint32_t offA[2][2], offB[4][2];
    #pragma unroll
    for (int mt = 0; mt < 2; mt++) {
        int row = wm + mt * 16 + (lane & 15);
        #pragma unroll
        for (int kk = 0; kk < 2; kk++) {
            int cs = kk * 2 + (lane >> 4);
            offA[mt][kk] = row * 64 + ((cs ^ ((row >> 1) & 3)) << 4);
        }
    }
    #pragma unroll
    for (int jb = 0; jb < 4; jb++) {
        int n = wn + jb * 16 + ((lane >> 4) << 3) + (lane & 7);
        #pragma unroll
        for (int kk = 0; kk < 2; kk++) {
            int cs = kk * 2 + ((lane >> 3) & 1);
            offB[jb][kk] = n * 64 + ((cs ^ ((n >> 1) & 3)) << 4);
        }
    }

    for (int c = 0; c < nchunk; c++) {
        const int s = c % STAGES;
        asm volatile("cp.async.wait_group 1;" ::: "memory");
        __syncthreads();

        const int nc = c + STAGES - 1;
        if (nc < nchunk) fill(nc, nc % STAGES);

        const uint32_t st = stg + s * STAGEW2_BYTES;
        #pragma unroll
        for (int kk = 0; kk < 2; kk++) {
            uint32_t a[2][4];
            ldsm4(a[0], st + offA[0][kk]);
            ldsm4(a[1], st + offA[1][kk]);
            #pragma unroll
            for (int jb = 0; jb < 4; jb++) {
                uint32_t bh[4], bl[4];
                ldsm4(bh, st + SUB_BYTES + offB[jb][kk]);
                ldsm4(bl, st + 2 * SUB_BYTES + offB[jb][kk]);
                #pragma unroll
                for (int half = 0; half < 2; half++) {
                    const int nt = 2 * jb + half;
                    #pragma unroll
                    for (int mt = 0; mt < 2; mt++) {
                        mma16816h(acc[mt][nt], a[mt], bh + 2 * half);
                        mma16816h(acc[mt][nt], a[mt], bl + 2 * half);
                    }
                }
            }
        }
    }

    const int r0 = bm + wm + (lane >> 2);
    const int cb0 = bn + wn + (lane & 3) * 2;
    #pragma unroll
    for (int mt = 0; mt < 2; mt++)
        #pragma unroll
        for (int nt = 0; nt < 8; nt++) {
            const int col = cb0 + nt * 8;
            const float bx = bias[col], by = bias[col + 1];
            #pragma unroll
            for (int half = 0; half < 2; half++) {
                const int row = r0 + mt * 16 + half * 8;
                float2 o;
                o.x = acc[mt][nt][half * 2 + 0] * ascale + bx;
                o.y = acc[mt][nt][half * 2 + 1] * ascale + by;
                *(float2*)(C + (size_t)row * ldc + col) = o;
            }
        }
}

// ================== fp16 single-pass GEMM (gate GEMMs) ===========================
// epi 1: C (fp32) = ux*sigmoid(y);  epi 2: vh (fp16) = VSCALE * ux*sigmoid(y)
#define HSTAGE_BYTES (2*SUB_BYTES)
#define HGEMM_SMEM   (STAGES*HSTAGE_BYTES)

__global__ void __launch_bounds__(256, 2) gemm_f16_k(
    const __half* __restrict__ A, const __half* __restrict__ B,
    const float* __restrict__ bias, float* __restrict__ C, int epi,
    const float* __restrict__ ux, __half* __restrict__ vh)
{
    extern __shared__ char smem[];
    const uint32_t stg = smem_u32(smem);
    const int tid = threadIdx.x, wid = tid >> 5, lane = tid & 31;
    const int bm = blockIdx.y * 128, bn = blockIdx.x * 128;
    const int wm = (wid & 3) * 32, wn = (wid >> 2) * 64;
    const int nchunk = KDIM / CHUNK_K;

    const __half* sA = A + (size_t)bm * KDIM;
    const __half* sB = B + (size_t)bn * KDIM;

    auto fill = [&](int chunk, int stage) {
        const uint32_t st = stg + stage * HSTAGE_BYTES;
        const int k0 = chunk * CHUNK_K;
        const __half* gs[2] = { sA, sB };
        #pragma unroll
        for (int sub = 0; sub < 2; sub++) {
            const __half* g = gs[sub] + k0;
            const uint32_t db = st + sub * SUB_BYTES;
            #pragma unroll
            for (int i = 0; i < 2; i++) {
                int idx = tid + i * 256;
                int row = idx >> 2, cs = idx & 3;
                const void* gp = g + (size_t)row * KDIM + cs * 8;
                uint32_t dp = db + row * 64 + ((cs ^ ((row >> 1) & 3)) << 4);
                asm volatile("cp.async.cg.shared.global [%0], [%1], 16;"
                             :: "r"(dp), "l"(gp) : "memory");
            }
        }
        asm volatile("cp.async.commit_group;" ::: "memory");
    };

    fill(0, 0);
    fill(1, 1);

    float acc[2][8][4];
    #pragma unroll
    for (int i = 0; i < 2; i++)
        #pragma unroll
        for (int j = 0; j < 8; j++)
            #pragma unroll
            for (int p = 0; p < 4; p++) acc[i][j][p] = 0.f;

    uint32_t offA[2][2], offB[4][2];
    #pragma unroll
    for (int mt = 0; mt < 2; mt++) {
        int row = wm + mt * 16 + (lane & 15);
        #pragma unroll
        for (int kk = 0; kk < 2; kk++) {
            int cs = kk * 2 + (lane >> 4);
            offA[mt][kk] = row * 64 + ((cs ^ ((row >> 1) & 3)) << 4);
        }
    }
    #pragma unroll
    for (int jb = 0; jb < 4; jb++) {
        int n = wn + jb * 16 + ((lane >> 4) << 3) + (lane & 7);
        #pragma unroll
        for (int kk = 0; kk < 2; kk++) {
            int cs = kk * 2 + ((lane >> 3) & 1);
            offB[jb][kk] = n * 64 + ((cs ^ ((n >> 1) & 3)) << 4);
        }
    }

    for (int c = 0; c < nchunk; c++) {
        const int s = c % STAGES;
        asm volatile("cp.async.wait_group 1;" ::: "memory");
        __syncthreads();

        const int nc = c + STAGES - 1;
        if (nc < nchunk) fill(nc, nc % STAGES);

        const uint32_t st = stg + s * HSTAGE_BYTES;
        #pragma unroll
        for (int kk = 0; kk < 2; kk++) {
            uint32_t a[2][4];
            ldsm4(a[0], st + offA[0][kk]);
            ldsm4(a[1], st + offA[1][kk]);
            #pragma unroll
            for (int jb = 0; jb < 4; jb++) {
                uint32_t bf[4];
                ldsm4(bf, st + SUB_BYTES + offB[jb][kk]);
                #pragma unroll
                for (int half = 0; half < 2; half++) {
                    const int nt = 2 * jb + half;
                    mma16816h(acc[0][nt], a[0], bf + 2 * half);
                    mma16816h(acc[1][nt], a[1], bf + 2 * half);
                }
            }
        }
    }

    const int r0 = bm + wm + (lane >> 2);
    const int cb0 = bn + wn + (lane & 3) * 2;
    #pragma unroll
    for (int mt = 0; mt < 2; mt++)
        #pragma unroll
        for (int nt = 0; nt < 8; nt++) {
            const int col = cb0 + nt * 8;
            const float bx = bias[col], by = bias[col + 1];
            #pragma unroll
            for (int half = 0; half < 2; half++) {
                const int row = r0 + mt * 16 + half * 8;
                float vx = acc[mt][nt][half * 2 + 0] + bx;
                float vy = acc[mt][nt][half * 2 + 1] + by;
                const size_t idx = (size_t)row * Dd + col;
                float2 pp = *(const float2*)(ux + idx);
                vx = pp.x * (1.0f / (1.0f + __expf(-vx)));
                vy = pp.y * (1.0f / (1.0f + __expf(-vy)));
                if (epi == 1) {
                    float2 o; o.x = vx; o.y = vy;
                    *(float2*)(C + idx) = o;
                } else {
                    // scale into fp16 normal range; 1/VSCALE folded into out GEMM
                    __half2 h;
                    h.x = __float2half(vx * VSCALE);
                    h.y = __float2half(vy * VSCALE);
                    *(__half2*)(vh + idx) = h;
                }
            }
        }
}

// ================== quant / transpose-split ======================================
__global__ void quantx_k(const float* __restrict__ s, __half* __restrict__ o, int n4) {
    int i = blockIdx.x * blockDim.x + threadIdx.x;
    if (i >= n4) return;
    float4 v = ((const float4*)s)[i];
    __half2 h0; h0.x = __float2half(v.x); h0.y = __float2half(v.y);
    __half2 h1; h1.x = __float2half(v.z); h1.y = __float2half(v.w);
    *(__half2*)(o + (size_t)i * 4)     = h0;
    *(__half2*)(o + (size_t)i * 4 + 2) = h1;
}

__global__ void tsplit_all_k(const float* __restrict__ ipw, const float* __restrict__ gw,
                             const float* __restrict__ opw,
                             __half* __restrict__ WIH, __half* __restrict__ WIL,
                             __half* __restrict__ WG,
                             __half* __restrict__ WOH, __half* __restrict__ WOL)
{
    __shared__ float tile[32][33];
    int gn0 = blockIdx.x * 32;
    int k0  = blockIdx.y * 32;
    int tx = threadIdx.x, ty = threadIdx.y;   // 32 x 8

    const float* W; int N; int nbase;
    if (gn0 < PROJ_N)            { W = ipw;                  N = PROJ_N; nbase = gn0; }
    else if (gn0 < PROJ_N + Dd)  { W = gw;                   N = Dd;     nbase = gn0 - PROJ_N; }
    else if (gn0 < PROJ_N + 2*Dd){ W = gw + (size_t)Dd * Dd; N = Dd;     nbase = gn0 - PROJ_N - Dd; }
    else                         { W = opw;                  N = Dd;     nbase = gn0 - PROJ_N - 2*Dd; }

    #pragma unroll
    for (int j = 0; j < 32; j += 8)
        tile[ty + j][tx] = W[(size_t)(k0 + ty + j) * N + nbase + tx];
    __syncthreads();
    #pragma unroll
    for (int j = 0; j < 32; j += 8) {
        int n = gn0 + ty + j, k = k0 + tx;
        float v = tile[tx][ty + j];
        __half h = __float2half(v);
        __half l = __float2half(v - __half2float(h));
        if (n < PROJ_N) {
            size_t o = (size_t)n * KDIM + k;
            WIH[o] = h; WIL[o] = l;
        } else if (n < PROJ_N + 2 * Dd) {
            WG[(size_t)(n - PROJ_N) * KDIM + k] = h;
        } else {
            size_t o = (size_t)(n - PROJ_N - 2 * Dd) * KDIM + k;
            WOH[o] = h; WOL[o] = l;
        }
    }
}

// ================== filter (d-parallel) ===========================================
__device__ __forceinline__ float gelu_exact(float x) {
    return 0.5f * x * (1.0f + erff(x * 0.70710678118654752f));
}

__global__ void filter_k(const float* __restrict__ freqs,
                         const float* __restrict__ w1, const float* __restrict__ b1,
                         const float* __restrict__ w2, const float* __restrict__ b2,
                         const float* __restrict__ w3, const float* __restrict__ b3,
                         const float* __restrict__ decay, int ord,
                         float* __restrict__ h)
{
    const int n   = blockIdx.x;
    const int d0  = blockIdx.y * 128;
    const int tid = threadIdx.x;               // 128 threads
    const float t = (float)n / (float)(Ls - 1);
    __shared__ float h1s[64];
    __shared__ float h2s[64];
    float enc[7];
    const float* f = freqs + ord * 3;
    #pragma unroll
    for (int j = 0; j < 3; j++) {
        float ang = 6.283185307179586f * f[j] * t;
        enc[j] = sinf(ang); enc[3 + j] = cosf(ang);
    }
    enc[6] = t;
    if (tid < 64) {
        float s = b1[ord * 64 + tid];
        #pragma unroll
        for (int k = 0; k < 7; k++) s += enc[k] * w1[(ord * 7 + k) * 64 + tid];
        h1s[tid] = gelu_exact(s);
    }
    __syncthreads();
    if (tid < 64) {
        float s = b2[ord * 64 + tid];
        for (int k = 0; k < 64; k++) s += h1s[k] * w2[(ord * 64 + k) * 64 + tid];
        h2s[tid] = gelu_exact(s);
    }
    __syncthreads();
    {
        int d = d0 + tid;
        float s = b3[(size_t)ord * Dd + d];
        #pragma unroll 8
        for (int k = 0; k < 64; k++) s += h2s[k] * w3[((size_t)ord * 64 + k) * Dd + d];
        float wind = expf(-fabsf(decay[(size_t)ord * Dd + d]) * t * (float)Ls);
        h[(size_t)n * Dd + d] = s * wind;
    }
}

// ================== merged convlong + conv3, fused ux = u*xc, fp16 xc =============
#define CT 32
__global__ void __launch_bounds__(128) convs_k(
    const float* __restrict__ vin, int vstride,
    const float* __restrict__ hflt,
    float* __restrict__ ux,
    const float* __restrict__ proj, int off,
    const float* __restrict__ w, const float* __restrict__ cb,
    __half* __restrict__ oh)
{
    __shared__ float vs[CT + TAPS - 1][128];
    const int tx = threadIdx.x;
    const int d  = blockIdx.x * 128 + tx;
    const int t0 = blockIdx.y * CT;
    const int b  = blockIdx.z;

    #pragma unroll 5
    for (int r = 0; r < CT + TAPS - 1; r++) {
        int t = t0 - (TAPS - 1) + r;
        vs[r][tx] = (t >= 0) ? vin[((size_t)b * Ls + t) * vstride + d] : 0.f;
    }
    __syncthreads();

    float acc[CT];
    #pragma unroll
    for (int j = 0; j < CT; j++) acc[j] = 0.f;
    #pragma unroll
    for (int l0 = 0; l0 < TAPS; l0 += 16) {
        float hr[16];
        #pragma unroll
        for (int l = 0; l < 16; l++) hr[l] = hflt[(size_t)(l0 + l) * Dd + d];
        float vv[CT + 15];
        #pragma unroll
        for (int p = 0; p < CT + 15; p++) vv[p] = vs[(TAPS - 1 - 15) - l0 + p][tx];
        #pragma unroll
        for (int l = 0; l < 16; l++)
            #pragma unroll
            for (int j = 0; j < CT; j++)
                acc[j] = fmaf(vv[15 + j - l], hr[l], acc[j]);
    }

    const float wl = w[d], wc = w[Dd + d], wr = w[2 * Dd + d], cbv = cb[d];
    const float* pbase = proj + ((size_t)b * Ls + t0) * PROJ_N + off + d;
    #pragma unroll 4
    for (int j = 0; j < CT; j++) {
        int t = t0 + j;
        const float* p = pbase + (size_t)j * PROJ_N;
        float s = cbv + p[0] * wc;
        if (t > 0)      s += p[-PROJ_N] * wl;
        if (t < Ls - 1) s += p[PROJ_N]  * wr;
        size_t idx = ((size_t)b * Ls + t) * Dd + d;
        ux[idx] = acc[j] * s;
        oh[idx] = __float2half(s);
    }
}

// =================================================================================
extern "C" void kernel_launch(void* const* d_in, const int* in_sizes, int n_in,
                              void* d_out, int out_size)
{
    const float* x    = (const float*)d_in[0];
    const float* ipw  = (const float*)d_in[1];
    const float* ipb  = (const float*)d_in[2];
    const float* opw  = (const float*)d_in[3];
    const float* opb  = (const float*)d_in[4];
    const float* fre  = (const float*)d_in[5];
    const float* w1   = (const float*)d_in[6];
    const float* b1   = (const float*)d_in[7];
    const float* w2   = (const float*)d_in[8];
    const float* b2   = (const float*)d_in[9];
    const float* w3   = (const float*)d_in[10];
    const float* b3   = (const float*)d_in[11];
    const float* dec  = (const float*)d_in[12];
    const float* cw   = (const float*)d_in[13];
    const float* cb   = (const float*)d_in[14];
    const float* gw   = (const float*)d_in[15];
    const float* gb   = (const float*)d_in[16];
    float* out = (float*)d_out;

    float *p_proj, *p_h, *p_v, *p_ux;
    __half *p_ah, *p_wih, *p_wil, *p_wh, *p_woh, *p_wol, *p_ch, *p_vh;
    cudaGetSymbolAddress((void**)&p_proj, g_proj);
    cudaGetSymbolAddress((void**)&p_h,    g_h);
    cudaGetSymbolAddress((void**)&p_v,    g_v);
    cudaGetSymbolAddress((void**)&p_ux,   g_ux);
    cudaGetSymbolAddress((void**)&p_ah,   g_ah);
    cudaGetSymbolAddress((void**)&p_wih,  g_wih);
    cudaGetSymbolAddress((void**)&p_wil,  g_wil);
    cudaGetSymbolAddress((void**)&p_wh,   g_wh);
    cudaGetSymbolAddress((void**)&p_woh,  g_woh);
    cudaGetSymbolAddress((void**)&p_wol,  g_wol);
    cudaGetSymbolAddress((void**)&p_ch,   g_ch);
    cudaGetSymbolAddress((void**)&p_vh,   g_vh);

    cudaFuncSetAttribute(gemm_f16w2_k, cudaFuncAttributeMaxDynamicSharedMemorySize, GEMMW2_SMEM);
    cudaFuncSetAttribute(gemm_f16_k,   cudaFuncAttributeMaxDynamicSharedMemorySize, HGEMM_SMEM);

    // quantize x to fp16
    {
        int n4 = Mrows * KDIM / 4;
        quantx_k<<<(n4 + 255) / 256, 256>>>(x, p_ah, n4);
    }
    // transpose + per-region quantize all weights
    {
        dim3 b(32, 8);
        tsplit_all_k<<<dim3(WROWS / 32, KDIM / 32), b>>>(ipw, gw, opw,
                                                         p_wih, p_wil, p_wh, p_woh, p_wol);
    }

    // 1) proj = x @ in_proj_w + b  (fp16 x-single, W-2comp)
    gemm_f16w2_k<<<dim3(PROJ_N / 128, Mrows / 128), 256, GEMMW2_SMEM>>>(
        p_ah, p_wih, p_wil, ipb, p_proj, PROJ_N, 1.0f);

    for (int i = 0; i < ORD; i++) {
        filter_k<<<dim3(TAPS, Dd / 128), 128>>>(fre, w1, b1, w2, b2, w3, b3, dec, i, p_h);

        const float* vin = (i == 0) ? p_proj : p_v;
        int vstride      = (i == 0) ? PROJ_N : Dd;
        dim3 gc(Dd / 128, Ls / CT, Bb);
        convs_k<<<gc, 128>>>(vin, vstride, p_h, p_ux,
                             p_proj, (i + 1) * Dd,
                             cw + (size_t)i * 3 * Dd, cb + (size_t)i * Dd,
                             p_ch);

        // gate GEMM (fp16 single-pass): v = ux * sigmoid(xc@gw + gb)
        gemm_f16_k<<<dim3(Dd / 128, Mrows / 128), 256, HGEMM_SMEM>>>(
            p_ch, p_wh + (size_t)i * Dd * KDIM,
            gb + (size_t)i * Dd, p_v, (i == 0) ? 1 : 2,
            p_ux, p_vh);
    }

    // 3) out = (1/VSCALE) * (vh @ out_proj_w) + b   (fp16 v-single scaled, W-2comp)
    gemm_f16w2_k<<<dim3(Dd / 128, Mrows / 128), 256, GEMMW2_SMEM>>>(
        p_vh, p_woh, p_wol, opb, out, Dd, VSCALE_INV);
}

// round 16
// speedup vs baseline: 1.6575x; 1.1627x over previous
#include <cuda_runtime.h>
#include <cuda_bf16.h>
#include <cuda_fp16.h>
#include <math.h>
#include <stdint.h>

// Problem constants
#define Bb     2
#define Ls     4096
#define Dd     1024
#define ORD    2
#define PROJ_N (3*Dd)
#define TAPS   64
#define Mrows  (Bb*Ls)
#define KDIM   1024
#define WROWS  (PROJ_N + 3*Dd)

#define VSCALE     256.0f
#define VSCALE_INV (1.0f/256.0f)

// ---------------- scratch (device globals) -------------------------------------
__device__ float g_proj[(size_t)Mrows*PROJ_N];
__device__ float g_h[(size_t)TAPS*Dd];
__device__ float g_v[(size_t)Mrows*Dd];
__device__ float g_ux[(size_t)Mrows*Dd];             // u * xc (pre-multiplied)
__device__ __half g_ah[(size_t)Mrows*KDIM];          // fp16 x
__device__ __half g_wih[(size_t)PROJ_N*KDIM];        // fp16 in_proj W (transposed, single)
__device__ __half g_wh[(size_t)2*Dd*KDIM];           // fp16 gate weights (transposed)
__device__ __half g_woh[(size_t)Dd*KDIM];            // fp16 out_proj W hi
__device__ __half g_wol[(size_t)Dd*KDIM];            // fp16 out_proj W lo
__device__ __half g_ch[(size_t)Mrows*KDIM];          // fp16 xc
__device__ __half g_vh[(size_t)Mrows*KDIM];          // fp16 256*v

// ---------------- helpers -------------------------------------------------------
__device__ __forceinline__ uint32_t smem_u32(const void* p) {
    uint32_t a;
    asm("{ .reg .u64 t; cvta.to.shared.u64 t, %1; cvt.u32.u64 %0, t; }" : "=r"(a) : "l"(p));
    return a;
}
__device__ __forceinline__ void ldsm4(uint32_t* r, uint32_t addr) {
    asm volatile("ldmatrix.sync.aligned.m8n8.x4.shared.b16 {%0,%1,%2,%3}, [%4];"
                 : "=r"(r[0]), "=r"(r[1]), "=r"(r[2]), "=r"(r[3]) : "r"(addr));
}
__device__ __forceinline__ void mma16816h(float* c, const uint32_t* a, const uint32_t* b) {
    asm volatile(
        "mma.sync.aligned.m16n8k16.row.col.f32.f16.f16.f32 "
        "{%0,%1,%2,%3}, {%4,%5,%6,%7}, {%8,%9}, {%0,%1,%2,%3};"
        : "+f"(c[0]), "+f"(c[1]), "+f"(c[2]), "+f"(c[3])
        : "r"(a[0]), "r"(a[1]), "r"(a[2]), "r"(a[3]), "r"(b[0]), "r"(b[1]));
}

#define STAGES      3
#define CHUNK_K     32
#define SUB_BYTES   8192

// ================== fp16 A-single x W-2comp GEMM (out_proj) ======================
// C = ascale * (A@[B0+B1]^T) + bias
#define STAGEW2_BYTES (3*SUB_BYTES)
#define GEMMW2_SMEM   (STAGES*STAGEW2_BYTES)

__global__ void __launch_bounds__(256, 2) gemm_f16w2_k(
    const __half* __restrict__ A,
    const __half* __restrict__ B0, const __half* __restrict__ B1,
    const float* __restrict__ bias, float* __restrict__ C, int ldc, float ascale)
{
    extern __shared__ char smem[];
    const uint32_t stg = smem_u32(smem);
    const int tid = threadIdx.x, wid = tid >> 5, lane = tid & 31;
    const int bm = blockIdx.y * 128, bn = blockIdx.x * 128;
    const int wm = (wid & 3) * 32, wn = (wid >> 2) * 64;
    const int nchunk = KDIM / CHUNK_K;

    const __half* sA  = A  + (size_t)bm * KDIM;
    const __half* sB0 = B0 + (size_t)bn * KDIM;
    const __half* sB1 = B1 + (size_t)bn * KDIM;

    auto fill = [&](int chunk, int stage) {
        const uint32_t st = stg + stage * STAGEW2_BYTES;
        const int k0 = chunk * CHUNK_K;
        const __half* gs[3] = { sA, sB0, sB1 };
        #pragma unroll
        for (int sub = 0; sub < 3; sub++) {
            const __half* g = gs[sub] + k0;
            const uint32_t db = st + sub * SUB_BYTES;
            #pragma unroll
            for (int i = 0; i < 2; i++) {
                int idx = tid + i * 256;
                int row = idx >> 2, cs = idx & 3;
                const void* gp = g + (size_t)row * KDIM + cs * 8;
                uint32_t dp = db + row * 64 + ((cs ^ ((row >> 1) & 3)) << 4);
                asm volatile("cp.async.cg.shared.global [%0], [%1], 16;"
                             :: "r"(dp), "l"(gp) : "memory");
            }
        }
        asm volatile("cp.async.commit_group;" ::: "memory");
    };

    fill(0, 0);
    fill(1, 1);

    float acc[2][8][4];
    #pragma unroll
    for (int i = 0; i < 2; i++)
        #pragma unroll
        for (int j = 0; j < 8; j++)
            #pragma unroll
            for (int p = 0; p < 4; p++) acc[i][j][p] = 0.f;

    uint32_t offA[2][2], offB[4][2];
    #pragma unroll
    for (int mt = 0; mt < 2; mt++) {
        int row = wm + mt * 16 + (lane & 15);
        #pragma unroll
        for (int kk = 0; kk < 2; kk++) {
            int cs = kk * 2 + (lane >> 4);
            offA[mt][kk] = row * 64 + ((cs ^ ((row >> 1) & 3)) << 4);
        }
    }
    #pragma unroll
    for (int jb = 0; jb < 4; jb++) {
        int n = wn + jb * 16 + ((lane >> 4) << 3) + (lane & 7);
        #pragma unroll
        for (int kk = 0; kk < 2; kk++) {
            int cs = kk * 2 + ((lane >> 3) & 1);
            offB[jb][kk] = n * 64 + ((cs ^ ((n >> 1) & 3)) << 4);
        }
    }

    for (int c = 0; c < nchunk; c++) {
        const int s = c % STAGES;
        asm volatile("cp.async.wait_group 1;" ::: "memory");
        __syncthreads();

        const int nc = c + STAGES - 1;
        if (nc < nchunk) fill(nc, nc % STAGES);

        const uint32_t st = stg + s * STAGEW2_BYTES;
        #pragma unroll
        for (int kk = 0; kk < 2; kk++) {
            uint32_t a[2][4];
            ldsm4(a[0], st + offA[0][kk]);
            ldsm4(a[1], st + offA[1][kk]);
            #pragma unroll
            for (int jb = 0; jb < 4; jb++) {
                uint32_t bh[4], bl[4];
                ldsm4(bh, st + SUB_BYTES + offB[jb][kk]);
                ldsm4(bl, st + 2 * SUB_BYTES + offB[jb][kk]);
                #pragma unroll
                for (int half = 0; half < 2; half++) {
                    const int nt = 2 * jb + half;
                    #pragma unroll
                    for (int mt = 0; mt < 2; mt++) {
                        mma16816h(acc[mt][nt], a[mt], bh + 2 * half);
                        mma16816h(acc[mt][nt], a[mt], bl + 2 * half);
                    }
                }
            }
        }
    }

    const int r0 = bm + wm + (lane >> 2);
    const int cb0 = bn + wn + (lane & 3) * 2;
    #pragma unroll
    for (int mt = 0; mt < 2; mt++)
        #pragma unroll
        for (int nt = 0; nt < 8; nt++) {
            const int col = cb0 + nt * 8;
            const float bx = bias[col], by = bias[col + 1];
            #pragma unroll
            for (int half = 0; half < 2; half++) {
                const int row = r0 + mt * 16 + half * 8;
                float2 o;
                o.x = acc[mt][nt][half * 2 + 0] * ascale + bx;
                o.y = acc[mt][nt][half * 2 + 1] * ascale + by;
                *(float2*)(C + (size_t)row * ldc + col) = o;
            }
        }
}

// ================== fp16 single-pass GEMM (in_proj + gate GEMMs) =================
// epi 0: C (fp32) = acc + bias                     (in_proj; ldc = PROJ_N)
// epi 1: C (fp32) = ux * sigmoid(acc+bias)          (gate iter 0; ldc = Dd)
// epi 2: vh (fp16) = VSCALE * ux * sigmoid(acc+bias) (gate iter 1)
#define HSTAGE_BYTES (2*SUB_BYTES)
#define HGEMM_SMEM   (STAGES*HSTAGE_BYTES)

__global__ void __launch_bounds__(256, 2) gemm_f16_k(
    const __half* __restrict__ A, const __half* __restrict__ B,
    const float* __restrict__ bias, float* __restrict__ C, int ldc, int epi,
    const float* __restrict__ ux, __half* __restrict__ vh)
{
    extern __shared__ char smem[];
    const uint32_t stg = smem_u32(smem);
    const int tid = threadIdx.x, wid = tid >> 5, lane = tid & 31;
    const int bm = blockIdx.y * 128, bn = blockIdx.x * 128;
    const int wm = (wid & 3) * 32, wn = (wid >> 2) * 64;
    const int nchunk = KDIM / CHUNK_K;

    const __half* sA = A + (size_t)bm * KDIM;
    const __half* sB = B + (size_t)bn * KDIM;

    auto fill = [&](int chunk, int stage) {
        const uint32_t st = stg + stage * HSTAGE_BYTES;
        const int k0 = chunk * CHUNK_K;
        const __half* gs[2] = { sA, sB };
        #pragma unroll
        for (int sub = 0; sub < 2; sub++) {
            const __half* g = gs[sub] + k0;
            const uint32_t db = st + sub * SUB_BYTES;
            #pragma unroll
            for (int i = 0; i < 2; i++) {
                int idx = tid + i * 256;
                int row = idx >> 2, cs = idx & 3;
                const void* gp = g + (size_t)row * KDIM + cs * 8;
                uint32_t dp = db + row * 64 + ((cs ^ ((row >> 1) & 3)) << 4);
                asm volatile("cp.async.cg.shared.global [%0], [%1], 16;"
                             :: "r"(dp), "l"(gp) : "memory");
            }
        }
        asm volatile("cp.async.commit_group;" ::: "memory");
    };

    fill(0, 0);
    fill(1, 1);

    float acc[2][8][4];
    #pragma unroll
    for (int i = 0; i < 2; i++)
        #pragma unroll
        for (int j = 0; j < 8; j++)
            #pragma unroll
            for (int p = 0; p < 4; p++) acc[i][j][p] = 0.f;

    uint32_t offA[2][2], offB[4][2];
    #pragma unroll
    for (int mt = 0; mt < 2; mt++) {
        int row = wm + mt * 16 + (lane & 15);
        #pragma unroll
        for (int kk = 0; kk < 2; kk++) {
            int cs = kk * 2 + (lane >> 4);
            offA[mt][kk] = row * 64 + ((cs ^ ((row >> 1) & 3)) << 4);
        }
    }
    #pragma unroll
    for (int jb = 0; jb < 4; jb++) {
        int n = wn + jb * 16 + ((lane >> 4) << 3) + (lane & 7);
        #pragma unroll
        for (int kk = 0; kk < 2; kk++) {
            int cs = kk * 2 + ((lane >> 3) & 1);
            offB[jb][kk] = n * 64 + ((cs ^ ((n >> 1) & 3)) << 4);
        }
    }

    for (int c = 0; c < nchunk; c++) {
        const int s = c % STAGES;
        asm volatile("cp.async.wait_group 1;" ::: "memory");
        __syncthreads();

        const int nc = c + STAGES - 1;
        if (nc < nchunk) fill(nc, nc % STAGES);

        const uint32_t st = stg + s * HSTAGE_BYTES;
        #pragma unroll
        for (int kk = 0; kk < 2; kk++) {
            uint32_t a[2][4];
            ldsm4(a[0], st + offA[0][kk]);
            ldsm4(a[1], st + offA[1][kk]);
            #pragma unroll
            for (int jb = 0; jb < 4; jb++) {
                uint32_t bf[4];
                ldsm4(bf, st + SUB_BYTES + offB[jb][kk]);
                #pragma unroll
                for (int half = 0; half < 2; half++) {
                    const int nt = 2 * jb + half;
                    mma16816h(acc[0][nt], a[0], bf + 2 * half);
                    mma16816h(acc[1][nt], a[1], bf + 2 * half);
                }
            }
        }
    }

    const int r0 = bm + wm + (lane >> 2);
    const int cb0 = bn + wn + (lane & 3) * 2;
    #pragma unroll
    for (int mt = 0; mt < 2; mt++)
        #pragma unroll
        for (int nt = 0; nt < 8; nt++) {
            const int col = cb0 + nt * 8;
            const float bx = bias[col], by = bias[col + 1];
            #pragma unroll
            for (int half = 0; half < 2; half++) {
                const int row = r0 + mt * 16 + half * 8;
                float vx = acc[mt][nt][half * 2 + 0] + bx;
                float vy = acc[mt][nt][half * 2 + 1] + by;
                if (epi == 0) {
                    float2 o; o.x = vx; o.y = vy;
                    *(float2*)(C + (size_t)row * ldc + col) = o;
                } else {
                    const size_t idx = (size_t)row * Dd + col;
                    float2 pp = *(const float2*)(ux + idx);
                    vx = pp.x * (1.0f / (1.0f + __expf(-vx)));
                    vy = pp.y * (1.0f / (1.0f + __expf(-vy)));
                    if (epi == 1) {
                        float2 o; o.x = vx; o.y = vy;
                        *(float2*)(C + idx) = o;
                    } else {
                        __half2 h;
                        h.x = __float2half(vx * VSCALE);
                        h.y = __float2half(vy * VSCALE);
                        *(__half2*)(vh + idx) = h;
                    }
                }
            }
        }
}

// ================== quant / transpose-split ======================================
__global__ void quantx_k(const float* __restrict__ s, __half* __restrict__ o, int n4) {
    int i = blockIdx.x * blockDim.x + threadIdx.x;
    if (i >= n4) return;
    float4 v = ((const float4*)s)[i];
    __half2 h0; h0.x = __float2half(v.x); h0.y = __float2half(v.y);
    __half2 h1; h1.x = __float2half(v.z); h1.y = __float2half(v.w);
    *(__half2*)(o + (size_t)i * 4)     = h0;
    *(__half2*)(o + (size_t)i * 4 + 2) = h1;
}

__global__ void tsplit_all_k(const float* __restrict__ ipw, const float* __restrict__ gw,
                             const float* __restrict__ opw,
                             __half* __restrict__ WI, __half* __restrict__ WG,
                             __half* __restrict__ WOH, __half* __restrict__ WOL)
{
    __shared__ float tile[32][33];
    int gn0 = blockIdx.x * 32;
    int k0  = blockIdx.y * 32;
    int tx = threadIdx.x, ty = threadIdx.y;   // 32 x 8

    const float* W; int N; int nbase;
    if (gn0 < PROJ_N)            { W = ipw;                  N = PROJ_N; nbase = gn0; }
    else if (gn0 < PROJ_N + Dd)  { W = gw;                   N = Dd;     nbase = gn0 - PROJ_N; }
    else if (gn0 < PROJ_N + 2*Dd){ W = gw + (size_t)Dd * Dd; N = Dd;     nbase = gn0 - PROJ_N - Dd; }
    else                         { W = opw;                  N = Dd;     nbase = gn0 - PROJ_N - 2*Dd; }

    #pragma unroll
    for (int j = 0; j < 32; j += 8)
        tile[ty + j][tx] = W[(size_t)(k0 + ty + j) * N + nbase + tx];
    __syncthreads();
    #pragma unroll
    for (int j = 0; j < 32; j += 8) {
        int n = gn0 + ty + j, k = k0 + tx;
        float v = tile[tx][ty + j];
        __half h = __float2half(v);
        if (n < PROJ_N) {
            WI[(size_t)n * KDIM + k] = h;
        } else if (n < PROJ_N + 2 * Dd) {
            WG[(size_t)(n - PROJ_N) * KDIM + k] = h;
        } else {
            size_t o = (size_t)(n - PROJ_N - 2 * Dd) * KDIM + k;
            WOH[o] = h;
            WOL[o] = __float2half(v - __half2float(h));
        }
    }
}

// ================== filter (d-parallel) ===========================================
__device__ __forceinline__ float gelu_exact(float x) {
    return 0.5f * x * (1.0f + erff(x * 0.70710678118654752f));
}

__global__ void filter_k(const float* __restrict__ freqs,
                         const float* __restrict__ w1, const float* __restrict__ b1,
                         const float* __restrict__ w2, const float* __restrict__ b2,
                         const float* __restrict__ w3, const float* __restrict__ b3,
                         const float* __restrict__ decay, int ord,
                         float* __restrict__ h)
{
    const int n   = blockIdx.x;
    const int d0  = blockIdx.y * 128;
    const int tid = threadIdx.x;               // 128 threads
    const float t = (float)n / (float)(Ls - 1);
    __shared__ float h1s[64];
    __shared__ float h2s[64];
    float enc[7];
    const float* f = freqs + ord * 3;
    #pragma unroll
    for (int j = 0; j < 3; j++) {
        float ang = 6.283185307179586f * f[j] * t;
        enc[j] = sinf(ang); enc[3 + j] = cosf(ang);
    }
    enc[6] = t;
    if (tid < 64) {
        float s = b1[ord * 64 + tid];
        #pragma unroll
        for (int k = 0; k < 7; k++) s += enc[k] * w1[(ord * 7 + k) * 64 + tid];
        h1s[tid] = gelu_exact(s);
    }
    __syncthreads();
    if (tid < 64) {
        float s = b2[ord * 64 + tid];
        for (int k = 0; k < 64; k++) s += h1s[k] * w2[(ord * 64 + k) * 64 + tid];
        h2s[tid] = gelu_exact(s);
    }
    __syncthreads();
    {
        int d = d0 + tid;
        float s = b3[(size_t)ord * Dd + d];
        #pragma unroll 8
        for (int k = 0; k < 64; k++) s += h2s[k] * w3[((size_t)ord * 64 + k) * Dd + d];
        float wind = expf(-fabsf(decay[(size_t)ord * Dd + d]) * t * (float)Ls);
        h[(size_t)n * Dd + d] = s * wind;
    }
}

// ================== merged convlong + conv3, fused ux = u*xc, fp16 xc =============
#define CT 32
__global__ void __launch_bounds__(128) convs_k(
    const float* __restrict__ vin, int vstride,
    const float* __restrict__ hflt,
    float* __restrict__ ux,
    const float* __restrict__ proj, int off,
    const float* __restrict__ w, const float* __restrict__ cb,
    __half* __restrict__ oh)
{
    __shared__ float vs[CT + TAPS - 1][128];
    const int tx = threadIdx.x;
    const int d  = blockIdx.x * 128 + tx;
    const int t0 = blockIdx.y * CT;
    const int b  = blockIdx.z;

    #pragma unroll 5
    for (int r = 0; r < CT + TAPS - 1; r++) {
        int t = t0 - (TAPS - 1) + r;
        vs[r][tx] = (t >= 0) ? vin[((size_t)b * Ls + t) * vstride + d] : 0.f;
    }
    __syncthreads();

    float acc[CT];
    #pragma unroll
    for (int j = 0; j < CT; j++) acc[j] = 0.f;
    #pragma unroll
    for (int l0 = 0; l0 < TAPS; l0 += 16) {
        float hr[16];
        #pragma unroll
        for (int l = 0; l < 16; l++) hr[l] = hflt[(size_t)(l0 + l) * Dd + d];
        float vv[CT + 15];
        #pragma unroll
        for (int p = 0; p < CT + 15; p++) vv[p] = vs[(TAPS - 1 - 15) - l0 + p][tx];
        #pragma unroll
        for (int l = 0; l < 16; l++)
            #pragma unroll
            for (int j = 0; j < CT; j++)
                acc[j] = fmaf(vv[15 + j - l], hr[l], acc[j]);
    }

    const float wl = w[d], wc = w[Dd + d], wr = w[2 * Dd + d], cbv = cb[d];
    const float* pbase = proj + ((size_t)b * Ls + t0) * PROJ_N + off + d;
    #pragma unroll 4
    for (int j = 0; j < CT; j++) {
        int t = t0 + j;
        const float* p = pbase + (size_t)j * PROJ_N;
        float s = cbv + p[0] * wc;
        if (t > 0)      s += p[-PROJ_N] * wl;
        if (t < Ls - 1) s += p[PROJ_N]  * wr;
        size_t idx = ((size_t)b * Ls + t) * Dd + d;
        ux[idx] = acc[j] * s;
        oh[idx] = __float2half(s);
    }
}

// =================================================================================
extern "C" void kernel_launch(void* const* d_in, const int* in_sizes, int n_in,
                              void* d_out, int out_size)
{
    const float* x    = (const float*)d_in[0];
    const float* ipw  = (const float*)d_in[1];
    const float* ipb  = (const float*)d_in[2];
    const float* opw  = (const float*)d_in[3];
    const float* opb  = (const float*)d_in[4];
    const float* fre  = (const float*)d_in[5];
    const float* w1   = (const float*)d_in[6];
    const float* b1   = (const float*)d_in[7];
    const float* w2   = (const float*)d_in[8];
    const float* b2   = (const float*)d_in[9];
    const float* w3   = (const float*)d_in[10];
    const float* b3   = (const float*)d_in[11];
    const float* dec  = (const float*)d_in[12];
    const float* cw   = (const float*)d_in[13];
    const float* cb   = (const float*)d_in[14];
    const float* gw   = (const float*)d_in[15];
    const float* gb   = (const float*)d_in[16];
    float* out = (float*)d_out;

    float *p_proj, *p_h, *p_v, *p_ux;
    __half *p_ah, *p_wih, *p_wh, *p_woh, *p_wol, *p_ch, *p_vh;
    cudaGetSymbolAddress((void**)&p_proj, g_proj);
    cudaGetSymbolAddress((void**)&p_h,    g_h);
    cudaGetSymbolAddress((void**)&p_v,    g_v);
    cudaGetSymbolAddress((void**)&p_ux,   g_ux);
    cudaGetSymbolAddress((void**)&p_ah,   g_ah);
    cudaGetSymbolAddress((void**)&p_wih,  g_wih);
    cudaGetSymbolAddress((void**)&p_wh,   g_wh);
    cudaGetSymbolAddress((void**)&p_woh,  g_woh);
    cudaGetSymbolAddress((void**)&p_wol,  g_wol);
    cudaGetSymbolAddress((void**)&p_ch,   g_ch);
    cudaGetSymbolAddress((void**)&p_vh,   g_vh);

    cudaFuncSetAttribute(gemm_f16w2_k, cudaFuncAttributeMaxDynamicSharedMemorySize, GEMMW2_SMEM);
    cudaFuncSetAttribute(gemm_f16_k,   cudaFuncAttributeMaxDynamicSharedMemorySize, HGEMM_SMEM);

    // quantize x to fp16
    {
        int n4 = Mrows * KDIM / 4;
        quantx_k<<<(n4 + 255) / 256, 256>>>(x, p_ah, n4);
    }
    // transpose + per-region quantize all weights
    {
        dim3 b(32, 8);
        tsplit_all_k<<<dim3(WROWS / 32, KDIM / 32), b>>>(ipw, gw, opw,
                                                         p_wih, p_wh, p_woh, p_wol);
    }

    // 1) proj = x @ in_proj_w + b  (fp16 single-pass)
    gemm_f16_k<<<dim3(PROJ_N / 128, Mrows / 128), 256, HGEMM_SMEM>>>(
        p_ah, p_wih, ipb, p_proj, PROJ_N, 0, nullptr, nullptr);

    for (int i = 0; i < ORD; i++) {
        filter_k<<<dim3(TAPS, Dd / 128), 128>>>(fre, w1, b1, w2, b2, w3, b3, dec, i, p_h);

        const float* vin = (i == 0) ? p_proj : p_v;
        int vstride      = (i == 0) ? PROJ_N : Dd;
        dim3 gc(Dd / 128, Ls / CT, Bb);
        convs_k<<<gc, 128>>>(vin, vstride, p_h, p_ux,
                             p_proj, (i + 1) * Dd,
                             cw + (size_t)i * 3 * Dd, cb + (size_t)i * Dd,
                             p_ch);

        // gate GEMM (fp16 single-pass): v = ux * sigmoid(xc@gw + gb)
        gemm_f16_k<<<dim3(Dd / 128, Mrows / 128), 256, HGEMM_SMEM>>>(
            p_ch, p_wh + (size_t)i * Dd * KDIM,
            gb + (size_t)i * Dd, p_v, Dd, (i == 0) ? 1 : 2,
            p_ux, p_vh);
    }

    // 3) out = (1/VSCALE) * (vh @ out_proj_w) + b   (fp16 v-single scaled, W-2comp)
    gemm_f16w2_k<<<dim3(Dd / 128, Mrows / 128), 256, GEMMW2_SMEM>>>(
        p_vh, p_woh, p_wol, opb, out, Dd, VSCALE_INV);
}

// round 17
// speedup vs baseline: 1.7615x; 1.0627x over previous
#include <cuda_runtime.h>
#include <cuda_bf16.h>
#include <cuda_fp16.h>
#include <math.h>
#include <stdint.h>

// Problem constants
#define Bb     2
#define Ls     4096
#define Dd     1024
#define ORD    2
#define PROJ_N (3*Dd)
#define TAPS   64
#define Mrows  (Bb*Ls)
#define KDIM   1024
#define WROWS  (PROJ_N + 3*Dd)

#define VSCALE     256.0f
#define VSCALE_INV (1.0f/256.0f)

// ---------------- scratch (device globals) -------------------------------------
__device__ float g_proj[(size_t)Mrows*PROJ_N];
__device__ float g_h[(size_t)TAPS*Dd];
__device__ float g_v[(size_t)Mrows*Dd];
__device__ float g_ux[(size_t)Mrows*Dd];             // u * xc (pre-multiplied)
__device__ __half g_ah[(size_t)Mrows*KDIM];          // fp16 x
__device__ __half g_wih[(size_t)PROJ_N*KDIM];        // fp16 in_proj W (transposed)
__device__ __half g_wh[(size_t)2*Dd*KDIM];           // fp16 gate weights (transposed)
__device__ __half g_woh[(size_t)Dd*KDIM];            // fp16 out_proj W (transposed)
__device__ __half g_ch[(size_t)Mrows*KDIM];          // fp16 xc
__device__ __half g_vh[(size_t)Mrows*KDIM];          // fp16 256*v

// ---------------- helpers -------------------------------------------------------
__device__ __forceinline__ uint32_t smem_u32(const void* p) {
    uint32_t a;
    asm("{ .reg .u64 t; cvta.to.shared.u64 t, %1; cvt.u32.u64 %0, t; }" : "=r"(a) : "l"(p));
    return a;
}
__device__ __forceinline__ void ldsm4(uint32_t* r, uint32_t addr) {
    asm volatile("ldmatrix.sync.aligned.m8n8.x4.shared.b16 {%0,%1,%2,%3}, [%4];"
                 : "=r"(r[0]), "=r"(r[1]), "=r"(r[2]), "=r"(r[3]) : "r"(addr));
}
__device__ __forceinline__ void mma16816h(float* c, const uint32_t* a, const uint32_t* b) {
    asm volatile(
        "mma.sync.aligned.m16n8k16.row.col.f32.f16.f16.f32 "
        "{%0,%1,%2,%3}, {%4,%5,%6,%7}, {%8,%9}, {%0,%1,%2,%3};"
        : "+f"(c[0]), "+f"(c[1]), "+f"(c[2]), "+f"(c[3])
        : "r"(a[0]), "r"(a[1]), "r"(a[2]), "r"(a[3]), "r"(b[0]), "r"(b[1]));
}

#define STAGES      3
#define CHUNK_K     32
#define SUB_BYTES   8192

// ================== fp16 single-pass GEMM (ALL GEMMs) ============================
// epi 0: C (fp32) = ascale*acc + bias               (in_proj ascale=1; out ascale=1/VSCALE)
// epi 1: C (fp32) = ux * sigmoid(acc+bias)           (gate iter 0)
// epi 2: vh (fp16) = VSCALE * ux * sigmoid(acc+bias) (gate iter 1)
#define HSTAGE_BYTES (2*SUB_BYTES)
#define HGEMM_SMEM   (STAGES*HSTAGE_BYTES)

__global__ void __launch_bounds__(256, 2) gemm_f16_k(
    const __half* __restrict__ A, const __half* __restrict__ B,
    const float* __restrict__ bias, float* __restrict__ C, int ldc, int epi, float ascale,
    const float* __restrict__ ux, __half* __restrict__ vh)
{
    extern __shared__ char smem[];
    const uint32_t stg = smem_u32(smem);
    const int tid = threadIdx.x, wid = tid >> 5, lane = tid & 31;
    const int bm = blockIdx.y * 128, bn = blockIdx.x * 128;
    const int wm = (wid & 3) * 32, wn = (wid >> 2) * 64;
    const int nchunk = KDIM / CHUNK_K;

    const __half* sA = A + (size_t)bm * KDIM;
    const __half* sB = B + (size_t)bn * KDIM;

    auto fill = [&](int chunk, int stage) {
        const uint32_t st = stg + stage * HSTAGE_BYTES;
        const int k0 = chunk * CHUNK_K;
        const __half* gs[2] = { sA, sB };
        #pragma unroll
        for (int sub = 0; sub < 2; sub++) {
            const __half* g = gs[sub] + k0;
            const uint32_t db = st + sub * SUB_BYTES;
            #pragma unroll
            for (int i = 0; i < 2; i++) {
                int idx = tid + i * 256;
                int row = idx >> 2, cs = idx & 3;
                const void* gp = g + (size_t)row * KDIM + cs * 8;
                uint32_t dp = db + row * 64 + ((cs ^ ((row >> 1) & 3)) << 4);
                asm volatile("cp.async.cg.shared.global [%0], [%1], 16;"
                             :: "r"(dp), "l"(gp) : "memory");
            }
        }
        asm volatile("cp.async.commit_group;" ::: "memory");
    };

    fill(0, 0);
    fill(1, 1);

    float acc[2][8][4];
    #pragma unroll
    for (int i = 0; i < 2; i++)
        #pragma unroll
        for (int j = 0; j < 8; j++)
            #pragma unroll
            for (int p = 0; p < 4; p++) acc[i][j][p] = 0.f;

    uint32_t offA[2][2], offB[4][2];
    #pragma unroll
    for (int mt = 0; mt < 2; mt++) {
        int row = wm + mt * 16 + (lane & 15);
        #pragma unroll
        for (int kk = 0; kk < 2; kk++) {
            int cs = kk * 2 + (lane >> 4);
            offA[mt][kk] = row * 64 + ((cs ^ ((row >> 1) & 3)) << 4);
        }
    }
    #pragma unroll
    for (int jb = 0; jb < 4; jb++) {
        int n = wn + jb * 16 + ((lane >> 4) << 3) + (lane & 7);
        #pragma unroll
        for (int kk = 0; kk < 2; kk++) {
            int cs = kk * 2 + ((lane >> 3) & 1);
            offB[jb][kk] = n * 64 + ((cs ^ ((n >> 1) & 3)) << 4);
        }
    }

    for (int c = 0; c < nchunk; c++) {
        const int s = c % STAGES;
        asm volatile("cp.async.wait_group 1;" ::: "memory");
        __syncthreads();

        const int nc = c + STAGES - 1;
        if (nc < nchunk) fill(nc, nc % STAGES);

        const uint32_t st = stg + s * HSTAGE_BYTES;
        #pragma unroll
        for (int kk = 0; kk < 2; kk++) {
            uint32_t a[2][4];
            ldsm4(a[0], st + offA[0][kk]);
            ldsm4(a[1], st + offA[1][kk]);
            #pragma unroll
            for (int jb = 0; jb < 4; jb++) {
                uint32_t bf[4];
                ldsm4(bf, st + SUB_BYTES + offB[jb][kk]);
                #pragma unroll
                for (int half = 0; half < 2; half++) {
                    const int nt = 2 * jb + half;
                    mma16816h(acc[0][nt], a[0], bf + 2 * half);
                    mma16816h(acc[1][nt], a[1], bf + 2 * half);
                }
            }
        }
    }

    const int r0 = bm + wm + (lane >> 2);
    const int cb0 = bn + wn + (lane & 3) * 2;
    #pragma unroll
    for (int mt = 0; mt < 2; mt++)
        #pragma unroll
        for (int nt = 0; nt < 8; nt++) {
            const int col = cb0 + nt * 8;
            const float bx = bias[col], by = bias[col + 1];
            #pragma unroll
            for (int half = 0; half < 2; half++) {
                const int row = r0 + mt * 16 + half * 8;
                if (epi == 0) {
                    float2 o;
                    o.x = acc[mt][nt][half * 2 + 0] * ascale + bx;
                    o.y = acc[mt][nt][half * 2 + 1] * ascale + by;
                    *(float2*)(C + (size_t)row * ldc + col) = o;
                } else {
                    float vx = acc[mt][nt][half * 2 + 0] + bx;
                    float vy = acc[mt][nt][half * 2 + 1] + by;
                    const size_t idx = (size_t)row * Dd + col;
                    float2 pp = *(const float2*)(ux + idx);
                    vx = pp.x * (1.0f / (1.0f + __expf(-vx)));
                    vy = pp.y * (1.0f / (1.0f + __expf(-vy)));
                    if (epi == 1) {
                        float2 o; o.x = vx; o.y = vy;
                        *(float2*)(C + idx) = o;
                    } else {
                        __half2 h;
                        h.x = __float2half(vx * VSCALE);
                        h.y = __float2half(vy * VSCALE);
                        *(__half2*)(vh + idx) = h;
                    }
                }
            }
        }
}

// ================== quant / transpose ============================================
__global__ void quantx_k(const float* __restrict__ s, __half* __restrict__ o, int n4) {
    int i = blockIdx.x * blockDim.x + threadIdx.x;
    if (i >= n4) return;
    float4 v = ((const float4*)s)[i];
    __half2 h0; h0.x = __float2half(v.x); h0.y = __float2half(v.y);
    __half2 h1; h1.x = __float2half(v.z); h1.y = __float2half(v.w);
    *(__half2*)(o + (size_t)i * 4)     = h0;
    *(__half2*)(o + (size_t)i * 4 + 2) = h1;
}

__global__ void tsplit_all_k(const float* __restrict__ ipw, const float* __restrict__ gw,
                             const float* __restrict__ opw,
                             __half* __restrict__ WI, __half* __restrict__ WG,
                             __half* __restrict__ WO)
{
    __shared__ float tile[32][33];
    int gn0 = blockIdx.x * 32;
    int k0  = blockIdx.y * 32;
    int tx = threadIdx.x, ty = threadIdx.y;   // 32 x 8

    const float* W; int N; int nbase;
    if (gn0 < PROJ_N)            { W = ipw;                  N = PROJ_N; nbase = gn0; }
    else if (gn0 < PROJ_N + Dd)  { W = gw;                   N = Dd;     nbase = gn0 - PROJ_N; }
    else if (gn0 < PROJ_N + 2*Dd){ W = gw + (size_t)Dd * Dd; N = Dd;     nbase = gn0 - PROJ_N - Dd; }
    else                         { W = opw;                  N = Dd;     nbase = gn0 - PROJ_N - 2*Dd; }

    #pragma unroll
    for (int j = 0; j < 32; j += 8)
        tile[ty + j][tx] = W[(size_t)(k0 + ty + j) * N + nbase + tx];
    __syncthreads();
    #pragma unroll
    for (int j = 0; j < 32; j += 8) {
        int n = gn0 + ty + j, k = k0 + tx;
        __half h = __float2half(tile[tx][ty + j]);
        if (n < PROJ_N)
            WI[(size_t)n * KDIM + k] = h;
        else if (n < PROJ_N + 2 * Dd)
            WG[(size_t)(n - PROJ_N) * KDIM + k] = h;
        else
            WO[(size_t)(n - PROJ_N - 2 * Dd) * KDIM + k] = h;
    }
}

// ================== filter (d-parallel) ===========================================
__device__ __forceinline__ float gelu_exact(float x) {
    return 0.5f * x * (1.0f + erff(x * 0.70710678118654752f));
}

__global__ void filter_k(const float* __restrict__ freqs,
                         const float* __restrict__ w1, const float* __restrict__ b1,
                         const float* __restrict__ w2, const float* __restrict__ b2,
                         const float* __restrict__ w3, const float* __restrict__ b3,
                         const float* __restrict__ decay, int ord,
                         float* __restrict__ h)
{
    const int n   = blockIdx.x;
    const int d0  = blockIdx.y * 128;
    const int tid = threadIdx.x;               // 128 threads
    const float t = (float)n / (float)(Ls - 1);
    __shared__ float h1s[64];
    __shared__ float h2s[64];
    float enc[7];
    const float* f = freqs + ord * 3;
    #pragma unroll
    for (int j = 0; j < 3; j++) {
        float ang = 6.283185307179586f * f[j] * t;
        enc[j] = sinf(ang); enc[3 + j] = cosf(ang);
    }
    enc[6] = t;
    if (tid < 64) {
        float s = b1[ord * 64 + tid];
        #pragma unroll
        for (int k = 0; k < 7; k++) s += enc[k] * w1[(ord * 7 + k) * 64 + tid];
        h1s[tid] = gelu_exact(s);
    }
    __syncthreads();
    if (tid < 64) {
        float s = b2[ord * 64 + tid];
        for (int k = 0; k < 64; k++) s += h1s[k] * w2[(ord * 64 + k) * 64 + tid];
        h2s[tid] = gelu_exact(s);
    }
    __syncthreads();
    {
        int d = d0 + tid;
        float s = b3[(size_t)ord * Dd + d];
        #pragma unroll 8
        for (int k = 0; k < 64; k++) s += h2s[k] * w3[((size_t)ord * 64 + k) * Dd + d];
        float wind = expf(-fabsf(decay[(size_t)ord * Dd + d]) * t * (float)Ls);
        h[(size_t)n * Dd + d] = s * wind;
    }
}

// ================== merged convlong + conv3, fused ux = u*xc, fp16 xc =============
#define CT 32
__global__ void __launch_bounds__(128) convs_k(
    const float* __restrict__ vin, int vstride,
    const float* __restrict__ hflt,
    float* __restrict__ ux,
    const float* __restrict__ proj, int off,
    const float* __restrict__ w, const float* __restrict__ cb,
    __half* __restrict__ oh)
{
    __shared__ float vs[CT + TAPS - 1][128];
    const int tx = threadIdx.x;
    const int d  = blockIdx.x * 128 + tx;
    const int t0 = blockIdx.y * CT;
    const int b  = blockIdx.z;

    #pragma unroll 5
    for (int r = 0; r < CT + TAPS - 1; r++) {
        int t = t0 - (TAPS - 1) + r;
        vs[r][tx] = (t >= 0) ? vin[((size_t)b * Ls + t) * vstride + d] : 0.f;
    }
    __syncthreads();

    float acc[CT];
    #pragma unroll
    for (int j = 0; j < CT; j++) acc[j] = 0.f;
    #pragma unroll
    for (int l0 = 0; l0 < TAPS; l0 += 16) {
        float hr[16];
        #pragma unroll
        for (int l = 0; l < 16; l++) hr[l] = hflt[(size_t)(l0 + l) * Dd + d];
        float vv[CT + 15];
        #pragma unroll
        for (int p = 0; p < CT + 15; p++) vv[p] = vs[(TAPS - 1 - 15) - l0 + p][tx];
        #pragma unroll
        for (int l = 0; l < 16; l++)
            #pragma unroll
            for (int j = 0; j < CT; j++)
                acc[j] = fmaf(vv[15 + j - l], hr[l], acc[j]);
    }

    const float wl = w[d], wc = w[Dd + d], wr = w[2 * Dd + d], cbv = cb[d];
    const float* pbase = proj + ((size_t)b * Ls + t0) * PROJ_N + off + d;
    #pragma unroll 4
    for (int j = 0; j < CT; j++) {
        int t = t0 + j;
        const float* p = pbase + (size_t)j * PROJ_N;
        float s = cbv + p[0] * wc;
        if (t > 0)      s += p[-PROJ_N] * wl;
        if (t < Ls - 1) s += p[PROJ_N]  * wr;
        size_t idx = ((size_t)b * Ls + t) * Dd + d;
        ux[idx] = acc[j] * s;
        oh[idx] = __float2half(s);
    }
}

// =================================================================================
extern "C" void kernel_launch(void* const* d_in, const int* in_sizes, int n_in,
                              void* d_out, int out_size)
{
    const float* x    = (const float*)d_in[0];
    const float* ipw  = (const float*)d_in[1];
    const float* ipb  = (const float*)d_in[2];
    const float* opw  = (const float*)d_in[3];
    const float* opb  = (const float*)d_in[4];
    const float* fre  = (const float*)d_in[5];
    const float* w1   = (const float*)d_in[6];
    const float* b1   = (const float*)d_in[7];
    const float* w2   = (const float*)d_in[8];
    const float* b2   = (const float*)d_in[9];
    const float* w3   = (const float*)d_in[10];
    const float* b3   = (const float*)d_in[11];
    const float* dec  = (const float*)d_in[12];
    const float* cw   = (const float*)d_in[13];
    const float* cb   = (const float*)d_in[14];
    const float* gw   = (const float*)d_in[15];
    const float* gb   = (const float*)d_in[16];
    float* out = (float*)d_out;

    float *p_proj, *p_h, *p_v, *p_ux;
    __half *p_ah, *p_wih, *p_wh, *p_woh, *p_ch, *p_vh;
    cudaGetSymbolAddress((void**)&p_proj, g_proj);
    cudaGetSymbolAddress((void**)&p_h,    g_h);
    cudaGetSymbolAddress((void**)&p_v,    g_v);
    cudaGetSymbolAddress((void**)&p_ux,   g_ux);
    cudaGetSymbolAddress((void**)&p_ah,   g_ah);
    cudaGetSymbolAddress((void**)&p_wih,  g_wih);
    cudaGetSymbolAddress((void**)&p_wh,   g_wh);
    cudaGetSymbolAddress((void**)&p_woh,  g_woh);
    cudaGetSymbolAddress((void**)&p_ch,   g_ch);
    cudaGetSymbolAddress((void**)&p_vh,   g_vh);

    cudaFuncSetAttribute(gemm_f16_k, cudaFuncAttributeMaxDynamicSharedMemorySize, HGEMM_SMEM);

    // quantize x to fp16
    {
        int n4 = Mrows * KDIM / 4;
        quantx_k<<<(n4 + 255) / 256, 256>>>(x, p_ah, n4);
    }
    // transpose + fp16-quantize all weights
    {
        dim3 b(32, 8);
        tsplit_all_k<<<dim3(WROWS / 32, KDIM / 32), b>>>(ipw, gw, opw, p_wih, p_wh, p_woh);
    }

    // 1) proj = x @ in_proj_w + b  (fp16 single-pass)
    gemm_f16_k<<<dim3(PROJ_N / 128, Mrows / 128), 256, HGEMM_SMEM>>>(
        p_ah, p_wih, ipb, p_proj, PROJ_N, 0, 1.0f, nullptr, nullptr);

    for (int i = 0; i < ORD; i++) {
        filter_k<<<dim3(TAPS, Dd / 128), 128>>>(fre, w1, b1, w2, b2, w3, b3, dec, i, p_h);

        const float* vin = (i == 0) ? p_proj : p_v;
        int vstride      = (i == 0) ? PROJ_N : Dd;
        dim3 gc(Dd / 128, Ls / CT, Bb);
        convs_k<<<gc, 128>>>(vin, vstride, p_h, p_ux,
                             p_proj, (i + 1) * Dd,
                             cw + (size_t)i * 3 * Dd, cb + (size_t)i * Dd,
                             p_ch);

        // gate GEMM (fp16 single-pass): v = ux * sigmoid(xc@gw + gb)
        gemm_f16_k<<<dim3(Dd / 128, Mrows / 128), 256, HGEMM_SMEM>>>(
            p_ch, p_wh + (size_t)i * Dd * KDIM,
            gb + (size_t)i * Dd, p_v, Dd, (i == 0) ? 1 : 2, 1.0f,
            p_ux, p_vh);
    }

    // 3) out = (1/VSCALE) * (vh @ out_proj_w) + b  (fp16 single-pass)
    gemm_f16_k<<<dim3(Dd / 128, Mrows / 128), 256, HGEMM_SMEM>>>(
        p_vh, p_woh, opb, out, Dd, 0, VSCALE_INV, nullptr, nullptr);
}